// round 6
// baseline (speedup 1.0000x reference)
#include <cuda_runtime.h>

#define NBLK 148
#define NTHR 448
#define NW   (NTHR / 32)

// ---------------- static device scratch (no runtime allocation) ----------------
__device__ __align__(16) float g_Wsum_f[4096 * 1024];
__device__ __align__(16) float g_Wsum_r[4096 * 1024];
__device__ __align__(16) float g_bsum_f[4096];
__device__ __align__(16) float g_bsum_r[4096];
__device__ __align__(16) float g_enc_bsum[8192];
__device__ __align__(16) float g_hf[2][2048];   // encoder fwd hidden (double buffered)
__device__ __align__(16) float g_hr[2][2048];   // encoder rev hidden
__device__ __align__(16) float g_common[512];
__device__ __align__(16) float g_h0f[1024];
__device__ __align__(16) float g_h0r[1024];
__device__ __align__(16) float g_dhf[2][1024];  // decoder f hidden
__device__ __align__(16) float g_dhr[2][1024];  // decoder r hidden
__device__ unsigned g_bar_cnt = 0;
__device__ unsigned g_bar_gen = 0;

// ---------------- grid barrier (sense via monotonically increasing gen) --------
__device__ __forceinline__ void gsync(unsigned target) {
    __syncthreads();
    if (threadIdx.x == 0) {
        __threadfence();
        unsigned a = atomicAdd(&g_bar_cnt, 1u);
        if (a == gridDim.x - 1) {
            atomicExch(&g_bar_cnt, 0u);
            __threadfence();
            atomicExch(&g_bar_gen, target);
        } else {
            volatile unsigned* p = &g_bar_gen;
            while ((int)(*p - target) < 0) { __nanosleep(64); }
        }
        __threadfence();
    }
    __syncthreads();
}

__device__ __forceinline__ float wredsum(float v) {
#pragma unroll
    for (int o = 16; o; o >>= 1) v += __shfl_xor_sync(0xffffffffu, v, o);
    return v;
}
__device__ __forceinline__ float sigmoidf_(float v) { return 1.0f / (1.0f + __expf(-v)); }
__device__ __forceinline__ float dot4(float4 a, float4 b) {
    return a.x * b.x + a.y * b.y + a.z * b.z + a.w * b.w;
}
// stage a run of floats (multiple of 4) into shared, bypassing L1 (fresh data)
__device__ __forceinline__ void stage4(float* dst, const float* src, int n4) {
    float4* d4 = (float4*)dst;
    const float4* s4 = (const float4*)src;
    for (int i = threadIdx.x; i < n4; i += NTHR) d4[i] = __ldcg(s4 + i);
}

__global__ void __launch_bounds__(NTHR)
ae_kernel(const int* __restrict__ x, const int* __restrict__ Vg, const int* __restrict__ Jg,
          const float* __restrict__ emb, const float* __restrict__ emb_Vg,
          const float* __restrict__ emb_Jg,
          const float* __restrict__ enc_Wih, const float* __restrict__ enc_Whh,
          const float* __restrict__ enc_bih, const float* __restrict__ enc_bhh,
          const float* __restrict__ cls_W, const float* __restrict__ cls_b,
          const float* __restrict__ latf_W, const float* __restrict__ latf_b,
          const float* __restrict__ latr_W, const float* __restrict__ latr_b,
          const float* __restrict__ mix_W, const float* __restrict__ mix_b,
          const float* __restrict__ recf_Wih, const float* __restrict__ recf_Whh,
          const float* __restrict__ recf_bih, const float* __restrict__ recf_bhh,
          const float* __restrict__ recr_Wih, const float* __restrict__ recr_Whh,
          const float* __restrict__ recr_bih, const float* __restrict__ recr_bhh,
          float* __restrict__ out) {
    __shared__ __align__(16) float sbuf[6144];
    const int tid = threadIdx.x;
    const int lane = tid & 31;
    const int gw = blockIdx.x * NW + (tid >> 5);
    const int gtid = blockIdx.x * NTHR + tid;
    const int gsz = NBLK * NTHR;

    float* out_recf = out + 1280;
    float* out_recr = out + 1280 + 262144;
    float* out_embf = out + 1280 + 2 * 262144;
    float* out_embr = out + 1280 + 3 * 262144;

    // barrier base: graph replays leave g_bar_gen at the previous total; all
    // threads read it before anyone can advance it (first advance requires all
    // blocks to reach barrier #1).
    unsigned bar = *(volatile unsigned*)&g_bar_gen;

    // ---------------- phase 0: precompute + gathers + init ----------------
    {
        const float4* a = (const float4*)recf_Wih;
        const float4* b = (const float4*)recf_Whh;
        float4* w = (float4*)g_Wsum_f;
        for (int i = gtid; i < (4096 * 1024 / 4); i += gsz) {
            float4 u = __ldg(a + i), v = __ldg(b + i);
            w[i] = make_float4(u.x + v.x, u.y + v.y, u.z + v.z, u.w + v.w);
        }
        a = (const float4*)recr_Wih;
        b = (const float4*)recr_Whh;
        w = (float4*)g_Wsum_r;
        for (int i = gtid; i < (4096 * 1024 / 4); i += gsz) {
            float4 u = __ldg(a + i), v = __ldg(b + i);
            w[i] = make_float4(u.x + v.x, u.y + v.y, u.z + v.z, u.w + v.w);
        }
    }
    for (int i = gtid; i < 4096; i += gsz) {
        g_bsum_f[i] = recf_bih[i] + recf_bhh[i];
        g_bsum_r[i] = recr_bih[i] + recr_bhh[i];
    }
    for (int i = gtid; i < 8192; i += gsz) g_enc_bsum[i] = enc_bih[i] + enc_bhh[i];
    for (int i = gtid; i < 256 * 1024; i += gsz) {
        int t = i >> 10, k = i & 1023;
        float v = emb[(x[t] << 10) + k];
        out_embf[i] = v;
        out_embr[((255 - t) << 10) + k] = v;
    }
    for (int k = gtid; k < 1024; k += gsz) {
        float e0 = emb[k], e1 = emb[1024 + k];
        out_recf[k] = e1;               // rec_f row 0   = end (emb[B_IDX=1])
        out_recf[255 * 1024 + k] = e0;  // rec_f row 255 = start (emb[X_IDX=0])
        out_recr[k] = e0;               // rec_r row 0   = end (emb[0])
        out_recr[255 * 1024 + k] = e1;  // rec_r row 255 = start (emb[1])
    }
    for (int k = gtid; k < 64; k += gsz) {
        float v = emb_Vg[(Vg[0] << 6) + k];
        g_h0f[k] = v; g_h0r[k] = v; out[k] = v; out[640 + k] = v;
        float jv = emb_Jg[(Jg[0] << 6) + k];
        g_h0f[576 + k] = jv; g_h0r[576 + k] = jv;
        out[576 + k] = jv; out[640 + 576 + k] = jv;
    }
    for (int k = gtid; k < 2048; k += gsz) { g_hf[0][k] = 0.f; g_hr[0][k] = 0.f; }
    bar++; gsync(bar);

    // ---------------- encoder: 256 steps, both directions share weights ----
    float ecf = 0.f, ecr = 0.f;
    const int j = gw;  // encoder hidden unit (valid if < 2048)
#pragma unroll 1
    for (int t = 0; t < 256; t++) {
        stage4(sbuf, out_embf + (t << 10), 256);               // x_f
        stage4(sbuf + 1024, out_embf + ((255 - t) << 10), 256);  // x_r
        stage4(sbuf + 2048, g_hf[t & 1], 512);
        stage4(sbuf + 4096, g_hr[t & 1], 512);
        __syncthreads();
        if (gw < 2048) {
            float af0 = 0.f, af1 = 0.f, af2 = 0.f, af3 = 0.f;
            float ar0 = 0.f, ar1 = 0.f, ar2 = 0.f, ar3 = 0.f;
            {
                const float4* W0 = (const float4*)(enc_Wih + (size_t)j * 1024);
                const float4* W1 = (const float4*)(enc_Wih + (size_t)(j + 2048) * 1024);
                const float4* W2 = (const float4*)(enc_Wih + (size_t)(j + 4096) * 1024);
                const float4* W3 = (const float4*)(enc_Wih + (size_t)(j + 6144) * 1024);
                const float4* XF = (const float4*)sbuf;
                const float4* XR = (const float4*)(sbuf + 1024);
#pragma unroll 2
                for (int i = lane; i < 256; i += 32) {
                    float4 xf = XF[i], xr = XR[i], w;
                    w = __ldg(W0 + i); af0 += dot4(w, xf); ar0 += dot4(w, xr);
                    w = __ldg(W1 + i); af1 += dot4(w, xf); ar1 += dot4(w, xr);
                    w = __ldg(W2 + i); af2 += dot4(w, xf); ar2 += dot4(w, xr);
                    w = __ldg(W3 + i); af3 += dot4(w, xf); ar3 += dot4(w, xr);
                }
            }
            {
                const float4* V0 = (const float4*)(enc_Whh + (size_t)j * 2048);
                const float4* V1 = (const float4*)(enc_Whh + (size_t)(j + 2048) * 2048);
                const float4* V2 = (const float4*)(enc_Whh + (size_t)(j + 4096) * 2048);
                const float4* V3 = (const float4*)(enc_Whh + (size_t)(j + 6144) * 2048);
                const float4* HF = (const float4*)(sbuf + 2048);
                const float4* HR = (const float4*)(sbuf + 4096);
#pragma unroll 2
                for (int i = lane; i < 512; i += 32) {
                    float4 hf = HF[i], hr = HR[i], w;
                    w = __ldg(V0 + i); af0 += dot4(w, hf); ar0 += dot4(w, hr);
                    w = __ldg(V1 + i); af1 += dot4(w, hf); ar1 += dot4(w, hr);
                    w = __ldg(V2 + i); af2 += dot4(w, hf); ar2 += dot4(w, hr);
                    w = __ldg(V3 + i); af3 += dot4(w, hf); ar3 += dot4(w, hr);
                }
            }
            af0 = wredsum(af0); af1 = wredsum(af1); af2 = wredsum(af2); af3 = wredsum(af3);
            ar0 = wredsum(ar0); ar1 = wredsum(ar1); ar2 = wredsum(ar2); ar3 = wredsum(ar3);
            float b0 = g_enc_bsum[j], b1 = g_enc_bsum[j + 2048];
            float b2 = g_enc_bsum[j + 4096], b3 = g_enc_bsum[j + 6144];
            float ig = sigmoidf_(af0 + b0), fg = sigmoidf_(af1 + b1);
            float gg = tanhf(af2 + b2), og = sigmoidf_(af3 + b3);
            ecf = fg * ecf + ig * gg;
            float hnf = og * tanhf(ecf);
            ig = sigmoidf_(ar0 + b0); fg = sigmoidf_(ar1 + b1);
            gg = tanhf(ar2 + b2);     og = sigmoidf_(ar3 + b3);
            ecr = fg * ecr + ig * gg;
            float hnr = og * tanhf(ecr);
            if (lane == 0) {
                g_hf[(t + 1) & 1][j] = hnf;
                g_hr[(t + 1) & 1][j] = hnr;
            }
        }
        bar++; gsync(bar);
    }

    // ---------------- glue phase 1: cls + lat_f + lat_r ----------------
    stage4(sbuf, g_hf[0], 512);         // hf at [0,2048)
    stage4(sbuf + 2048, g_hr[0], 512);  // hr at [2048,4096) -> concat layout
    __syncthreads();
    if (gw < 512) {
        int row = gw;
        const float4* W = (const float4*)(cls_W + (size_t)row * 4096);
        const float4* S = (const float4*)sbuf;
        float acc = 0.f;
        for (int i = lane; i < 1024; i += 32) acc += dot4(__ldg(W + i), S[i]);
        acc = wredsum(acc);
        if (lane == 0) g_common[row] = tanhf(acc + cls_b[row]);
    } else if (gw < 1024) {
        int row = gw - 512;
        const float4* W = (const float4*)(latf_W + (size_t)row * 2048);
        const float4* S = (const float4*)sbuf;
        float acc = 0.f;
        for (int i = lane; i < 512; i += 32) acc += dot4(__ldg(W + i), S[i]);
        acc = wredsum(acc);
        if (lane == 0) { float v = acc + latf_b[row]; g_h0f[64 + row] = v; out[64 + row] = v; }
    } else if (gw < 1536) {
        int row = gw - 1024;
        const float4* W = (const float4*)(latr_W + (size_t)row * 2048);
        const float4* S = (const float4*)(sbuf + 2048);
        float acc = 0.f;
        for (int i = lane; i < 512; i += 32) acc += dot4(__ldg(W + i), S[i]);
        acc = wredsum(acc);
        if (lane == 0) { float v = acc + latr_b[row]; g_h0r[64 + row] = v; out[640 + 64 + row] = v; }
    }
    bar++; gsync(bar);

    // ---------------- glue phase 2: mix ----------------
    stage4(sbuf, g_common, 128);
    __syncthreads();
    if (gw < 384) {
        int row = gw;
        const float4* W = (const float4*)(mix_W + (size_t)row * 512);
        const float4* S = (const float4*)sbuf;
        float acc = 0.f;
        for (int i = lane; i < 128; i += 32) acc += dot4(__ldg(W + i), S[i]);
        acc = wredsum(acc);
        if (lane == 0) { float v = acc + mix_b[row]; g_h0f[640 + row] = v; g_h0r[640 + row] = v; }
    }
    bar++; gsync(bar);

    // ---------------- decoders: 254 steps, both decoders in parallel ----------
    const int d = (gw >= 1024) ? 1 : 0;
    const int dj = gw - (d << 10);
    float dcc = 0.f;
#pragma unroll 1
    for (int s = 1; s <= 254; s++) {
        if (s == 1) {
            stage4(sbuf, emb, 256);                 // start_f = emb[0]
            stage4(sbuf + 1024, g_h0f, 256);
            stage4(sbuf + 2048, emb + 1024, 256);   // start_r = emb[1]
            stage4(sbuf + 3072, g_h0r, 256);
        } else {
            stage4(sbuf, g_dhf[s & 1], 256);
            stage4(sbuf + 2048, g_dhr[s & 1], 256);
        }
        __syncthreads();
        if (gw < 2048) {
            float a0 = 0.f, a1 = 0.f, a2 = 0.f, a3 = 0.f;
            const float4* X = (const float4*)(sbuf + (d << 11));
            if (s == 1) {
                const float* Wih = d ? recr_Wih : recf_Wih;
                const float* Whh = d ? recr_Whh : recf_Whh;
                const float4* P0 = (const float4*)(Wih + (size_t)dj * 1024);
                const float4* P1 = (const float4*)(Wih + (size_t)(dj + 1024) * 1024);
                const float4* P2 = (const float4*)(Wih + (size_t)(dj + 2048) * 1024);
                const float4* P3 = (const float4*)(Wih + (size_t)(dj + 3072) * 1024);
#pragma unroll 2
                for (int i = lane; i < 256; i += 32) {
                    float4 xv = X[i], w;
                    w = __ldg(P0 + i); a0 += dot4(w, xv);
                    w = __ldg(P1 + i); a1 += dot4(w, xv);
                    w = __ldg(P2 + i); a2 += dot4(w, xv);
                    w = __ldg(P3 + i); a3 += dot4(w, xv);
                }
                const float4* H = (const float4*)(sbuf + (d << 11) + 1024);
                const float4* Q0 = (const float4*)(Whh + (size_t)dj * 1024);
                const float4* Q1 = (const float4*)(Whh + (size_t)(dj + 1024) * 1024);
                const float4* Q2 = (const float4*)(Whh + (size_t)(dj + 2048) * 1024);
                const float4* Q3 = (const float4*)(Whh + (size_t)(dj + 3072) * 1024);
#pragma unroll 2
                for (int i = lane; i < 256; i += 32) {
                    float4 hv = H[i], w;
                    w = __ldg(Q0 + i); a0 += dot4(w, hv);
                    w = __ldg(Q1 + i); a1 += dot4(w, hv);
                    w = __ldg(Q2 + i); a2 += dot4(w, hv);
                    w = __ldg(Q3 + i); a3 += dot4(w, hv);
                }
                dcc = sbuf[(d << 11) + 1024 + dj];  // c0 = h0 vector value
            } else {
                const float* W = d ? g_Wsum_r : g_Wsum_f;
                const float4* P0 = (const float4*)(W + (size_t)dj * 1024);
                const float4* P1 = (const float4*)(W + (size_t)(dj + 1024) * 1024);
                const float4* P2 = (const float4*)(W + (size_t)(dj + 2048) * 1024);
                const float4* P3 = (const float4*)(W + (size_t)(dj + 3072) * 1024);
#pragma unroll 2
                for (int i = lane; i < 256; i += 32) {
                    float4 xv = X[i], w;
                    w = __ldg(P0 + i); a0 += dot4(w, xv);
                    w = __ldg(P1 + i); a1 += dot4(w, xv);
                    w = __ldg(P2 + i); a2 += dot4(w, xv);
                    w = __ldg(P3 + i); a3 += dot4(w, xv);
                }
            }
            a0 = wredsum(a0); a1 = wredsum(a1); a2 = wredsum(a2); a3 = wredsum(a3);
            const float* bs = d ? g_bsum_r : g_bsum_f;
            float ig = sigmoidf_(a0 + bs[dj]);
            float fg = sigmoidf_(a1 + bs[dj + 1024]);
            float gg = tanhf(a2 + bs[dj + 2048]);
            float og = sigmoidf_(a3 + bs[dj + 3072]);
            dcc = fg * dcc + ig * gg;
            float h2 = og * tanhf(dcc);
            if (lane == 0) {
                float* dh = d ? g_dhr[(s + 1) & 1] : g_dhf[(s + 1) & 1];
                dh[dj] = h2;
                float* orow = (d ? out_recr : out_recf) + (size_t)(255 - s) * 1024;
                orow[dj] = h2;
            }
        }
        bar++; gsync(bar);
    }
}

extern "C" void kernel_launch(void* const* d_in, const int* in_sizes, int n_in,
                              void* d_out, int out_size) {
    (void)in_sizes; (void)n_in; (void)out_size;
    ae_kernel<<<NBLK, NTHR>>>(
        (const int*)d_in[0], (const int*)d_in[1], (const int*)d_in[2],
        (const float*)d_in[3], (const float*)d_in[4], (const float*)d_in[5],
        (const float*)d_in[6], (const float*)d_in[7], (const float*)d_in[8],
        (const float*)d_in[9], (const float*)d_in[10], (const float*)d_in[11],
        (const float*)d_in[12], (const float*)d_in[13], (const float*)d_in[14],
        (const float*)d_in[15], (const float*)d_in[16], (const float*)d_in[17],
        (const float*)d_in[18], (const float*)d_in[19], (const float*)d_in[20],
        (const float*)d_in[21], (const float*)d_in[22], (const float*)d_in[23],
        (const float*)d_in[24], (const float*)d_in[25],
        (float*)d_out);
}

// round 8
// speedup vs baseline: 1.6464x; 1.6464x over previous
#include <cuda_runtime.h>

#define NBLK 148
#define NTHR 448
#define NW   (NTHR / 32)
#define TW   (NBLK * NW)

// ---------------- static device scratch (no runtime allocation) ----------------
__device__ __align__(16) short g_Whh_q[8192 * 2048];     // encoder Whh, int16 (33.5MB)
__device__ __align__(16) short g_Wsum_f_q[4096 * 1024];  // recf Wih+Whh, int16 (8.4MB)
__device__ __align__(16) short g_Wsum_r_q[4096 * 1024];  // recr Wih+Whh, int16 (8.4MB)
__device__ __align__(16) float g_enc_scale[8192];        // per-row dequant scale
__device__ __align__(16) float g_dsc_f[4096];
__device__ __align__(16) float g_dsc_r[4096];
__device__ __align__(16) float g_gatesx[256 * 8192];     // enc_Wih@x + bias, all t (8.4MB)
__device__ __align__(16) float g_bsum_f[4096];
__device__ __align__(16) float g_bsum_r[4096];
__device__ __align__(16) float g_enc_bsum[8192];
__device__ __align__(16) float g_hf[2][2048];   // encoder fwd hidden (double buffered)
__device__ __align__(16) float g_hr[2][2048];   // encoder rev hidden
__device__ __align__(16) float g_common[512];
__device__ __align__(16) float g_h0f[1024];
__device__ __align__(16) float g_h0r[1024];
__device__ __align__(16) float g_dhf[2][1024];  // decoder f hidden
__device__ __align__(16) float g_dhr[2][1024];  // decoder r hidden
__device__ unsigned g_bar_cnt = 0;
__device__ unsigned g_bar_gen = 0;

// ---------------- grid barrier (sense via monotonically increasing gen) --------
__device__ __forceinline__ void gsync(unsigned target) {
    __syncthreads();
    if (threadIdx.x == 0) {
        __threadfence();
        unsigned a = atomicAdd(&g_bar_cnt, 1u);
        if (a == gridDim.x - 1) {
            atomicExch(&g_bar_cnt, 0u);
            __threadfence();
            atomicExch(&g_bar_gen, target);
        } else {
            volatile unsigned* p = &g_bar_gen;
            while ((int)(*p - target) < 0) { __nanosleep(64); }
        }
        __threadfence();
    }
    __syncthreads();
}

__device__ __forceinline__ float wredsum(float v) {
#pragma unroll
    for (int o = 16; o; o >>= 1) v += __shfl_xor_sync(0xffffffffu, v, o);
    return v;
}
__device__ __forceinline__ float wredmax(float v) {
#pragma unroll
    for (int o = 16; o; o >>= 1) v = fmaxf(v, __shfl_xor_sync(0xffffffffu, v, o));
    return v;
}
__device__ __forceinline__ float sigmoidf_(float v) { return 1.0f / (1.0f + __expf(-v)); }
__device__ __forceinline__ float dot4(float4 a, float4 b) {
    return a.x * b.x + a.y * b.y + a.z * b.z + a.w * b.w;
}
// stage a run of floats (multiple of 4) into shared, bypassing L1 (fresh data)
__device__ __forceinline__ void stage4(float* dst, const float* src, int n4) {
    float4* d4 = (float4*)dst;
    const float4* s4 = (const float4*)src;
    for (int i = threadIdx.x; i < n4; i += NTHR) d4[i] = __ldcg(s4 + i);
}
// int16x8 weights: dual-direction accumulate (raw integer-valued dot; scale later)
__device__ __forceinline__ void acc8x2q(float& af, float& ar, uint4 w,
                                        float4 f0, float4 f1, float4 r0, float4 r1) {
    float c0 = (float)(short)(w.x);
    float c1 = (float)((short)(w.x >> 16));
    float c2 = (float)(short)(w.y);
    float c3 = (float)((short)(w.y >> 16));
    float c4 = (float)(short)(w.z);
    float c5 = (float)((short)(w.z >> 16));
    float c6 = (float)(short)(w.w);
    float c7 = (float)((short)(w.w >> 16));
    af += c0 * f0.x + c1 * f0.y + c2 * f0.z + c3 * f0.w
        + c4 * f1.x + c5 * f1.y + c6 * f1.z + c7 * f1.w;
    ar += c0 * r0.x + c1 * r0.y + c2 * r0.z + c3 * r0.w
        + c4 * r1.x + c5 * r1.y + c6 * r1.z + c7 * r1.w;
}
__device__ __forceinline__ float dot8q(uint4 w, float4 x0, float4 x1) {
    float c0 = (float)(short)(w.x);
    float c1 = (float)((short)(w.x >> 16));
    float c2 = (float)(short)(w.y);
    float c3 = (float)((short)(w.y >> 16));
    float c4 = (float)(short)(w.z);
    float c5 = (float)((short)(w.z >> 16));
    float c6 = (float)(short)(w.w);
    float c7 = (float)((short)(w.w >> 16));
    return c0 * x0.x + c1 * x0.y + c2 * x0.z + c3 * x0.w
         + c4 * x1.x + c5 * x1.y + c6 * x1.z + c7 * x1.w;
}
__device__ __forceinline__ unsigned pack2q(float a, float b, float inv) {
    int q0 = __float2int_rn(a * inv);
    int q1 = __float2int_rn(b * inv);
    return (unsigned)(q0 & 0xffff) | ((unsigned)q1 << 16);
}

__global__ void __launch_bounds__(NTHR)
ae_kernel(const int* __restrict__ x, const int* __restrict__ Vg, const int* __restrict__ Jg,
          const float* __restrict__ emb, const float* __restrict__ emb_Vg,
          const float* __restrict__ emb_Jg,
          const float* __restrict__ enc_Wih, const float* __restrict__ enc_Whh,
          const float* __restrict__ enc_bih, const float* __restrict__ enc_bhh,
          const float* __restrict__ cls_W, const float* __restrict__ cls_b,
          const float* __restrict__ latf_W, const float* __restrict__ latf_b,
          const float* __restrict__ latr_W, const float* __restrict__ latr_b,
          const float* __restrict__ mix_W, const float* __restrict__ mix_b,
          const float* __restrict__ recf_Wih, const float* __restrict__ recf_Whh,
          const float* __restrict__ recf_bih, const float* __restrict__ recf_bhh,
          const float* __restrict__ recr_Wih, const float* __restrict__ recr_Whh,
          const float* __restrict__ recr_bih, const float* __restrict__ recr_bhh,
          float* __restrict__ out) {
    __shared__ __align__(16) float sbuf[8192];   // 32KB
    const int tid = threadIdx.x;
    const int lane = tid & 31;
    const int wlocal = tid >> 5;
    const int gw = blockIdx.x * NW + wlocal;
    const int gtid = blockIdx.x * NTHR + tid;
    const int gsz = NBLK * NTHR;

    float* out_recf = out + 1280;
    float* out_recr = out + 1280 + 262144;
    float* out_embf = out + 1280 + 2 * 262144;
    float* out_embr = out + 1280 + 3 * 262144;

    // barrier base: graph replays leave g_bar_gen at the previous total.
    unsigned bar = *(volatile unsigned*)&g_bar_gen;

    // ---------------- phase 0: int16 quantization + gathers + init ----------------
    // encoder Whh -> int16, per-row scale (warp per row)
    for (int r = gw; r < 8192; r += TW) {
        const float4* src = (const float4*)(enc_Whh + (size_t)r * 2048);
        float m = 0.f;
        for (int i = lane; i < 512; i += 32) {
            float4 v = __ldg(src + i);
            m = fmaxf(m, fmaxf(fmaxf(fabsf(v.x), fabsf(v.y)), fmaxf(fabsf(v.z), fabsf(v.w))));
        }
        m = wredmax(m);
        if (m == 0.f) m = 1.f;
        float inv = 32767.0f / m;
        if (lane == 0) g_enc_scale[r] = m / 32767.0f;
        uint2* dst = (uint2*)(g_Whh_q + (size_t)r * 2048);
        for (int i = lane; i < 512; i += 32) {
            float4 v = __ldg(src + i);
            uint2 o2;
            o2.x = pack2q(v.x, v.y, inv);
            o2.y = pack2q(v.z, v.w, inv);
            dst[i] = o2;
        }
    }
    // decoder Wsum = Wih + Whh -> int16, per-row scale (8192 row-tasks, d = r>>12)
    for (int r = gw; r < 8192; r += TW) {
        const int d = r >> 12, row = r & 4095;
        const float4* A = (const float4*)((d ? recr_Wih : recf_Wih) + (size_t)row * 1024);
        const float4* B = (const float4*)((d ? recr_Whh : recf_Whh) + (size_t)row * 1024);
        float m = 0.f;
        for (int i = lane; i < 256; i += 32) {
            float4 a = __ldg(A + i), b = __ldg(B + i);
            float sx = a.x + b.x, sy = a.y + b.y, sz = a.z + b.z, sw = a.w + b.w;
            m = fmaxf(m, fmaxf(fmaxf(fabsf(sx), fabsf(sy)), fmaxf(fabsf(sz), fabsf(sw))));
        }
        m = wredmax(m);
        if (m == 0.f) m = 1.f;
        float inv = 32767.0f / m;
        if (lane == 0) (d ? g_dsc_r : g_dsc_f)[row] = m / 32767.0f;
        uint2* dst = (uint2*)((d ? g_Wsum_r_q : g_Wsum_f_q) + (size_t)row * 1024);
        for (int i = lane; i < 256; i += 32) {
            float4 a = __ldg(A + i), b = __ldg(B + i);
            uint2 o2;
            o2.x = pack2q(a.x + b.x, a.y + b.y, inv);
            o2.y = pack2q(a.z + b.z, a.w + b.w, inv);
            dst[i] = o2;
        }
    }
    for (int i = gtid; i < 4096; i += gsz) {
        g_bsum_f[i] = recf_bih[i] + recf_bhh[i];
        g_bsum_r[i] = recr_bih[i] + recr_bhh[i];
    }
    for (int i = gtid; i < 8192; i += gsz) g_enc_bsum[i] = enc_bih[i] + enc_bhh[i];
    for (int i = gtid; i < 256 * 1024; i += gsz) {
        int t = i >> 10, k = i & 1023;
        float v = emb[(x[t] << 10) + k];
        out_embf[i] = v;
        out_embr[((255 - t) << 10) + k] = v;
    }
    for (int k = gtid; k < 1024; k += gsz) {
        float e0 = emb[k], e1 = emb[1024 + k];
        out_recf[k] = e1;               // rec_f row 0   = end (emb[B_IDX=1])
        out_recf[255 * 1024 + k] = e0;  // rec_f row 255 = start (emb[X_IDX=0])
        out_recr[k] = e0;               // rec_r row 0   = end (emb[0])
        out_recr[255 * 1024 + k] = e1;  // rec_r row 255 = start (emb[1])
    }
    for (int k = gtid; k < 64; k += gsz) {
        float v = emb_Vg[(Vg[0] << 6) + k];
        g_h0f[k] = v; g_h0r[k] = v; out[k] = v; out[640 + k] = v;
        float jv = emb_Jg[(Jg[0] << 6) + k];
        g_h0f[576 + k] = jv; g_h0r[576 + k] = jv;
        out[576 + k] = jv; out[640 + 576 + k] = jv;
    }
    for (int k = gtid; k < 2048; k += gsz) { g_hf[0][k] = 0.f; g_hr[0][k] = 0.f; }
    bar++; gsync(bar);

    // ---------------- phase 0b: gates_x GEMM  (enc_Wih @ emb_f + bsum, all 256 t) ----
    // 128 blocks: tc = t-chunk of 8 timesteps (32 chunks), rg = 2048-row group (4 groups)
    if (blockIdx.x < 128) {
        const int tc = blockIdx.x & 31;
        const int rg = blockIdx.x >> 5;
        {   // stage x[8][1024] fp32 into smem
            const float4* src = (const float4*)(out_embf + (size_t)tc * 8 * 1024);
            float4* d4 = (float4*)sbuf;
            for (int i = tid; i < 2048; i += NTHR) d4[i] = __ldcg(src + i);
        }
        __syncthreads();
        const float4* SX = (const float4*)sbuf;
        const int rend = rg * 2048 + 2048;
        for (int r = rg * 2048 + wlocal; r < rend; r += NW) {
            const float4* W = (const float4*)(enc_Wih + (size_t)r * 1024);
            float a0 = 0.f, a1 = 0.f, a2 = 0.f, a3 = 0.f;
            float a4 = 0.f, a5 = 0.f, a6 = 0.f, a7 = 0.f;
#pragma unroll 4
            for (int i = lane; i < 256; i += 32) {
                float4 w = __ldg(W + i);
                a0 += dot4(w, SX[i]);        a1 += dot4(w, SX[256 + i]);
                a2 += dot4(w, SX[512 + i]);  a3 += dot4(w, SX[768 + i]);
                a4 += dot4(w, SX[1024 + i]); a5 += dot4(w, SX[1280 + i]);
                a6 += dot4(w, SX[1536 + i]); a7 += dot4(w, SX[1792 + i]);
            }
            a0 = wredsum(a0); a1 = wredsum(a1); a2 = wredsum(a2); a3 = wredsum(a3);
            a4 = wredsum(a4); a5 = wredsum(a5); a6 = wredsum(a6); a7 = wredsum(a7);
            if (lane == 0) {
                float b = g_enc_bsum[r];
                float* gp = g_gatesx + r;
                gp[(size_t)(tc * 8 + 0) * 8192] = a0 + b;
                gp[(size_t)(tc * 8 + 1) * 8192] = a1 + b;
                gp[(size_t)(tc * 8 + 2) * 8192] = a2 + b;
                gp[(size_t)(tc * 8 + 3) * 8192] = a3 + b;
                gp[(size_t)(tc * 8 + 4) * 8192] = a4 + b;
                gp[(size_t)(tc * 8 + 5) * 8192] = a5 + b;
                gp[(size_t)(tc * 8 + 6) * 8192] = a6 + b;
                gp[(size_t)(tc * 8 + 7) * 8192] = a7 + b;
            }
        }
    }
    bar++; gsync(bar);

    // ---------------- encoder: 256 steps, Whh-only (int16), both directions ----
    float ecf = 0.f, ecr = 0.f;
    const int j = gw;  // encoder hidden unit (valid if < 2048)
    float esc0 = 0.f, esc1 = 0.f, esc2 = 0.f, esc3 = 0.f;
    const uint4 *V0 = 0, *V1 = 0, *V2 = 0, *V3 = 0;
    if (gw < 2048) {
        esc0 = __ldg(&g_enc_scale[j]);
        esc1 = __ldg(&g_enc_scale[j + 2048]);
        esc2 = __ldg(&g_enc_scale[j + 4096]);
        esc3 = __ldg(&g_enc_scale[j + 6144]);
        V0 = (const uint4*)(g_Whh_q + (size_t)j * 2048);
        V1 = (const uint4*)(g_Whh_q + (size_t)(j + 2048) * 2048);
        V2 = (const uint4*)(g_Whh_q + (size_t)(j + 4096) * 2048);
        V3 = (const uint4*)(g_Whh_q + (size_t)(j + 6144) * 2048);
    }
#pragma unroll 1
    for (int t = 0; t < 256; t++) {
        stage4(sbuf, g_hf[t & 1], 512);          // hf at floats [0,2048)
        stage4(sbuf + 2048, g_hr[t & 1], 512);   // hr at floats [2048,4096)
        __syncthreads();
        if (gw < 2048) {
            float af0 = 0.f, af1 = 0.f, af2 = 0.f, af3 = 0.f;
            float ar0 = 0.f, ar1 = 0.f, ar2 = 0.f, ar3 = 0.f;
            const float4* HF = (const float4*)sbuf;
            const float4* HR = (const float4*)(sbuf + 2048);
#pragma unroll 2
            for (int i = lane; i < 256; i += 32) {
                float4 f0 = HF[2 * i], f1 = HF[2 * i + 1];
                float4 r0 = HR[2 * i], r1 = HR[2 * i + 1];
                acc8x2q(af0, ar0, __ldg(V0 + i), f0, f1, r0, r1);
                acc8x2q(af1, ar1, __ldg(V1 + i), f0, f1, r0, r1);
                acc8x2q(af2, ar2, __ldg(V2 + i), f0, f1, r0, r1);
                acc8x2q(af3, ar3, __ldg(V3 + i), f0, f1, r0, r1);
            }
            af0 = wredsum(af0); af1 = wredsum(af1); af2 = wredsum(af2); af3 = wredsum(af3);
            ar0 = wredsum(ar0); ar1 = wredsum(ar1); ar2 = wredsum(ar2); ar3 = wredsum(ar3);
            const float* gxf = g_gatesx + (size_t)t * 8192 + j;
            const float* gxr = g_gatesx + (size_t)(255 - t) * 8192 + j;
            float ig = sigmoidf_(af0 * esc0 + __ldg(gxf));
            float fg = sigmoidf_(af1 * esc1 + __ldg(gxf + 2048));
            float gg = tanhf(af2 * esc2 + __ldg(gxf + 4096));
            float og = sigmoidf_(af3 * esc3 + __ldg(gxf + 6144));
            ecf = fg * ecf + ig * gg;
            float hnf = og * tanhf(ecf);
            ig = sigmoidf_(ar0 * esc0 + __ldg(gxr));
            fg = sigmoidf_(ar1 * esc1 + __ldg(gxr + 2048));
            gg = tanhf(ar2 * esc2 + __ldg(gxr + 4096));
            og = sigmoidf_(ar3 * esc3 + __ldg(gxr + 6144));
            ecr = fg * ecr + ig * gg;
            float hnr = og * tanhf(ecr);
            if (lane == 0) {
                g_hf[(t + 1) & 1][j] = hnf;
                g_hr[(t + 1) & 1][j] = hnr;
            }
        }
        bar++; gsync(bar);
    }

    // ---------------- glue phase 1: cls + lat_f + lat_r ----------------
    stage4(sbuf, g_hf[0], 512);         // hf at [0,2048)
    stage4(sbuf + 2048, g_hr[0], 512);  // hr at [2048,4096) -> concat layout
    __syncthreads();
    if (gw < 512) {
        int row = gw;
        const float4* W = (const float4*)(cls_W + (size_t)row * 4096);
        const float4* S = (const float4*)sbuf;
        float acc = 0.f;
        for (int i = lane; i < 1024; i += 32) acc += dot4(__ldg(W + i), S[i]);
        acc = wredsum(acc);
        if (lane == 0) g_common[row] = tanhf(acc + cls_b[row]);
    } else if (gw < 1024) {
        int row = gw - 512;
        const float4* W = (const float4*)(latf_W + (size_t)row * 2048);
        const float4* S = (const float4*)sbuf;
        float acc = 0.f;
        for (int i = lane; i < 512; i += 32) acc += dot4(__ldg(W + i), S[i]);
        acc = wredsum(acc);
        if (lane == 0) { float v = acc + latf_b[row]; g_h0f[64 + row] = v; out[64 + row] = v; }
    } else if (gw < 1536) {
        int row = gw - 1024;
        const float4* W = (const float4*)(latr_W + (size_t)row * 2048);
        const float4* S = (const float4*)(sbuf + 2048);
        float acc = 0.f;
        for (int i = lane; i < 512; i += 32) acc += dot4(__ldg(W + i), S[i]);
        acc = wredsum(acc);
        if (lane == 0) { float v = acc + latr_b[row]; g_h0r[64 + row] = v; out[640 + 64 + row] = v; }
    }
    bar++; gsync(bar);

    // ---------------- glue phase 2: mix ----------------
    stage4(sbuf, g_common, 128);
    __syncthreads();
    if (gw < 384) {
        int row = gw;
        const float4* W = (const float4*)(mix_W + (size_t)row * 512);
        const float4* S = (const float4*)sbuf;
        float acc = 0.f;
        for (int i = lane; i < 128; i += 32) acc += dot4(__ldg(W + i), S[i]);
        acc = wredsum(acc);
        if (lane == 0) { float v = acc + mix_b[row]; g_h0f[640 + row] = v; g_h0r[640 + row] = v; }
    }
    bar++; gsync(bar);

    // ---------------- decoders: 254 steps, both decoders in parallel ----------
    const int d = (gw >= 1024) ? 1 : 0;
    const int dj = gw - (d << 10);
    float dcc = 0.f;
    float dsc0 = 0.f, dsc1 = 0.f, dsc2 = 0.f, dsc3 = 0.f;
    float bs0 = 0.f, bs1 = 0.f, bs2 = 0.f, bs3 = 0.f;
    const uint4 *P0 = 0, *P1 = 0, *P2 = 0, *P3 = 0;
    if (gw < 2048) {
        const float* dsc = d ? g_dsc_r : g_dsc_f;
        dsc0 = __ldg(&dsc[dj]);        dsc1 = __ldg(&dsc[dj + 1024]);
        dsc2 = __ldg(&dsc[dj + 2048]); dsc3 = __ldg(&dsc[dj + 3072]);
        const float* bs = d ? g_bsum_r : g_bsum_f;
        bs0 = __ldg(&bs[dj]);        bs1 = __ldg(&bs[dj + 1024]);
        bs2 = __ldg(&bs[dj + 2048]); bs3 = __ldg(&bs[dj + 3072]);
        const short* W = d ? g_Wsum_r_q : g_Wsum_f_q;
        P0 = (const uint4*)(W + (size_t)dj * 1024);
        P1 = (const uint4*)(W + (size_t)(dj + 1024) * 1024);
        P2 = (const uint4*)(W + (size_t)(dj + 2048) * 1024);
        P3 = (const uint4*)(W + (size_t)(dj + 3072) * 1024);
    }
#pragma unroll 1
    for (int s = 1; s <= 254; s++) {
        if (s == 1) {
            stage4(sbuf, emb, 256);                 // start_f = emb[0]
            stage4(sbuf + 1024, g_h0f, 256);
            stage4(sbuf + 2048, emb + 1024, 256);   // start_r = emb[1]
            stage4(sbuf + 3072, g_h0r, 256);
        } else {
            stage4(sbuf, g_dhf[s & 1], 256);
            stage4(sbuf + 2048, g_dhr[s & 1], 256);
        }
        __syncthreads();
        if (gw < 2048) {
            float a0 = 0.f, a1 = 0.f, a2 = 0.f, a3 = 0.f;
            const float4* X = (const float4*)(sbuf + (d << 11));
            if (s == 1) {
                // first step: prev != h, use original fp32 weights (one-time cost)
                const float* Wih = d ? recr_Wih : recf_Wih;
                const float* Whh = d ? recr_Whh : recf_Whh;
                const float4* R0 = (const float4*)(Wih + (size_t)dj * 1024);
                const float4* R1 = (const float4*)(Wih + (size_t)(dj + 1024) * 1024);
                const float4* R2 = (const float4*)(Wih + (size_t)(dj + 2048) * 1024);
                const float4* R3 = (const float4*)(Wih + (size_t)(dj + 3072) * 1024);
#pragma unroll 2
                for (int i = lane; i < 256; i += 32) {
                    float4 xv = X[i], w;
                    w = __ldg(R0 + i); a0 += dot4(w, xv);
                    w = __ldg(R1 + i); a1 += dot4(w, xv);
                    w = __ldg(R2 + i); a2 += dot4(w, xv);
                    w = __ldg(R3 + i); a3 += dot4(w, xv);
                }
                const float4* H = (const float4*)(sbuf + (d << 11) + 1024);
                const float4* Q0 = (const float4*)(Whh + (size_t)dj * 1024);
                const float4* Q1 = (const float4*)(Whh + (size_t)(dj + 1024) * 1024);
                const float4* Q2 = (const float4*)(Whh + (size_t)(dj + 2048) * 1024);
                const float4* Q3 = (const float4*)(Whh + (size_t)(dj + 3072) * 1024);
#pragma unroll 2
                for (int i = lane; i < 256; i += 32) {
                    float4 hv = H[i], w;
                    w = __ldg(Q0 + i); a0 += dot4(w, hv);
                    w = __ldg(Q1 + i); a1 += dot4(w, hv);
                    w = __ldg(Q2 + i); a2 += dot4(w, hv);
                    w = __ldg(Q3 + i); a3 += dot4(w, hv);
                }
                dcc = sbuf[(d << 11) + 1024 + dj];  // c0 = h0 vector value
            } else {
#pragma unroll 2
                for (int i = lane; i < 128; i += 32) {
                    float4 x0 = X[2 * i], x1 = X[2 * i + 1];
                    a0 += dot8q(__ldg(P0 + i), x0, x1);
                    a1 += dot8q(__ldg(P1 + i), x0, x1);
                    a2 += dot8q(__ldg(P2 + i), x0, x1);
                    a3 += dot8q(__ldg(P3 + i), x0, x1);
                }
                a0 *= dsc0; a1 *= dsc1; a2 *= dsc2; a3 *= dsc3;
            }
            a0 = wredsum(a0); a1 = wredsum(a1); a2 = wredsum(a2); a3 = wredsum(a3);
            float ig = sigmoidf_(a0 + bs0);
            float fg = sigmoidf_(a1 + bs1);
            float gg = tanhf(a2 + bs2);
            float og = sigmoidf_(a3 + bs3);
            dcc = fg * dcc + ig * gg;
            float h2 = og * tanhf(dcc);
            if (lane == 0) {
                float* dh = d ? g_dhr[(s + 1) & 1] : g_dhf[(s + 1) & 1];
                dh[dj] = h2;
                float* orow = (d ? out_recr : out_recf) + (size_t)(255 - s) * 1024;
                orow[dj] = h2;
            }
        }
        bar++; gsync(bar);
    }
}

extern "C" void kernel_launch(void* const* d_in, const int* in_sizes, int n_in,
                              void* d_out, int out_size) {
    (void)in_sizes; (void)n_in; (void)out_size;
    ae_kernel<<<NBLK, NTHR>>>(
        (const int*)d_in[0], (const int*)d_in[1], (const int*)d_in[2],
        (const float*)d_in[3], (const float*)d_in[4], (const float*)d_in[5],
        (const float*)d_in[6], (const float*)d_in[7], (const float*)d_in[8],
        (const float*)d_in[9], (const float*)d_in[10], (const float*)d_in[11],
        (const float*)d_in[12], (const float*)d_in[13], (const float*)d_in[14],
        (const float*)d_in[15], (const float*)d_in[16], (const float*)d_in[17],
        (const float*)d_in[18], (const float*)d_in[19], (const float*)d_in[20],
        (const float*)d_in[21], (const float*)d_in[22], (const float*)d_in[23],
        (const float*)d_in[24], (const float*)d_in[25],
        (float*)d_out);
}

// round 9
// speedup vs baseline: 1.8712x; 1.1366x over previous
#include <cuda_runtime.h>

#define NBLK 148
#define NTHR 896
#define NW   (NTHR / 32)
#define TW   (NBLK * NW)

// ---------------- static device scratch (no runtime allocation) ----------------
__device__ __align__(16) short g_Whh_q[8192 * 2048];     // encoder Whh, int16 (33.5MB)
__device__ __align__(16) short g_Wsum_f_q[4096 * 1024];  // recf Wih+Whh, int16 (8.4MB)
__device__ __align__(16) short g_Wsum_r_q[4096 * 1024];  // recr Wih+Whh, int16 (8.4MB)
__device__ __align__(16) float g_enc_scale[8192];        // per-row dequant scale
__device__ __align__(16) float g_dsc_f[4096];
__device__ __align__(16) float g_dsc_r[4096];
__device__ __align__(16) float g_gatesx[256 * 8192];     // enc_Wih@x + bias, all t (8.4MB)
__device__ __align__(16) float g_bsum_f[4096];
__device__ __align__(16) float g_bsum_r[4096];
__device__ __align__(16) float g_enc_bsum[8192];
__device__ __align__(16) float g_hf[2][2048];   // encoder fwd hidden (double buffered)
__device__ __align__(16) float g_hr[2][2048];   // encoder rev hidden
__device__ __align__(16) float g_common[512];
__device__ __align__(16) float g_h0f[1024];
__device__ __align__(16) float g_h0r[1024];
__device__ __align__(16) float g_dhf[2][1024];  // decoder f hidden
__device__ __align__(16) float g_dhr[2][1024];  // decoder r hidden
__device__ unsigned g_bar_cnt = 0;
__device__ unsigned g_bar_gen = 0;

// ---------------- grid barrier (sense via monotonically increasing gen) --------
__device__ __forceinline__ void gsync(unsigned target) {
    __syncthreads();
    if (threadIdx.x == 0) {
        __threadfence();
        unsigned a = atomicAdd(&g_bar_cnt, 1u);
        if (a == gridDim.x - 1) {
            atomicExch(&g_bar_cnt, 0u);
            __threadfence();
            atomicExch(&g_bar_gen, target);
        } else {
            volatile unsigned* p = &g_bar_gen;
            while ((int)(*p - target) < 0) { __nanosleep(32); }
        }
        __threadfence();
    }
    __syncthreads();
}

__device__ __forceinline__ float wredsum(float v) {
#pragma unroll
    for (int o = 16; o; o >>= 1) v += __shfl_xor_sync(0xffffffffu, v, o);
    return v;
}
__device__ __forceinline__ float wredmax(float v) {
#pragma unroll
    for (int o = 16; o; o >>= 1) v = fmaxf(v, __shfl_xor_sync(0xffffffffu, v, o));
    return v;
}
__device__ __forceinline__ float sigmoidf_(float v) { return 1.0f / (1.0f + __expf(-v)); }
__device__ __forceinline__ float dot4(float4 a, float4 b) {
    return a.x * b.x + a.y * b.y + a.z * b.z + a.w * b.w;
}
// stage a run of floats (multiple of 4) into shared, bypassing L1 (fresh data)
__device__ __forceinline__ void stage4(float* dst, const float* src, int n4) {
    float4* d4 = (float4*)dst;
    const float4* s4 = (const float4*)src;
    for (int i = threadIdx.x; i < n4; i += NTHR) d4[i] = __ldcg(s4 + i);
}
// int16x8 weights: dual-direction accumulate (raw integer-valued dot; scale later)
__device__ __forceinline__ void acc8x2q(float& af, float& ar, uint4 w,
                                        float4 f0, float4 f1, float4 r0, float4 r1) {
    float c0 = (float)(short)(w.x);
    float c1 = (float)((short)(w.x >> 16));
    float c2 = (float)(short)(w.y);
    float c3 = (float)((short)(w.y >> 16));
    float c4 = (float)(short)(w.z);
    float c5 = (float)((short)(w.z >> 16));
    float c6 = (float)(short)(w.w);
    float c7 = (float)((short)(w.w >> 16));
    af += c0 * f0.x + c1 * f0.y + c2 * f0.z + c3 * f0.w
        + c4 * f1.x + c5 * f1.y + c6 * f1.z + c7 * f1.w;
    ar += c0 * r0.x + c1 * r0.y + c2 * r0.z + c3 * r0.w
        + c4 * r1.x + c5 * r1.y + c6 * r1.z + c7 * r1.w;
}
__device__ __forceinline__ float dot8q(uint4 w, float4 x0, float4 x1) {
    float c0 = (float)(short)(w.x);
    float c1 = (float)((short)(w.x >> 16));
    float c2 = (float)(short)(w.y);
    float c3 = (float)((short)(w.y >> 16));
    float c4 = (float)(short)(w.z);
    float c5 = (float)((short)(w.z >> 16));
    float c6 = (float)(short)(w.w);
    float c7 = (float)((short)(w.w >> 16));
    return c0 * x0.x + c1 * x0.y + c2 * x0.z + c3 * x0.w
         + c4 * x1.x + c5 * x1.y + c6 * x1.z + c7 * x1.w;
}
__device__ __forceinline__ unsigned pack2q(float a, float b, float inv) {
    int q0 = __float2int_rn(a * inv);
    int q1 = __float2int_rn(b * inv);
    return (unsigned)(q0 & 0xffff) | ((unsigned)q1 << 16);
}

__global__ void __launch_bounds__(NTHR)
ae_kernel(const int* __restrict__ x, const int* __restrict__ Vg, const int* __restrict__ Jg,
          const float* __restrict__ emb, const float* __restrict__ emb_Vg,
          const float* __restrict__ emb_Jg,
          const float* __restrict__ enc_Wih, const float* __restrict__ enc_Whh,
          const float* __restrict__ enc_bih, const float* __restrict__ enc_bhh,
          const float* __restrict__ cls_W, const float* __restrict__ cls_b,
          const float* __restrict__ latf_W, const float* __restrict__ latf_b,
          const float* __restrict__ latr_W, const float* __restrict__ latr_b,
          const float* __restrict__ mix_W, const float* __restrict__ mix_b,
          const float* __restrict__ recf_Wih, const float* __restrict__ recf_Whh,
          const float* __restrict__ recf_bih, const float* __restrict__ recf_bhh,
          const float* __restrict__ recr_Wih, const float* __restrict__ recr_Whh,
          const float* __restrict__ recr_bih, const float* __restrict__ recr_bhh,
          float* __restrict__ out) {
    __shared__ __align__(16) float sbuf[8192];   // 32KB
    __shared__ __align__(16) float spar[14][8];  // split-K partials (unit-local)
    const int tid = threadIdx.x;
    const int lane = tid & 31;
    const int wlocal = tid >> 5;
    const int gw = blockIdx.x * NW + wlocal;
    const int gtid = blockIdx.x * NTHR + tid;
    const int gsz = NBLK * NTHR;

    // split-K pairing: two consecutive warps serve one unit/task
    const int uL = wlocal >> 1;                     // unit index within block (0..13)
    const int half = wlocal & 1;                    // K-half this warp covers
    const int u = blockIdx.x * 14 + uL;             // global unit/task id

    float* out_recf = out + 1280;
    float* out_recr = out + 1280 + 262144;
    float* out_embf = out + 1280 + 2 * 262144;
    float* out_embr = out + 1280 + 3 * 262144;

    // barrier base: graph replays leave g_bar_gen at the previous total.
    unsigned bar = *(volatile unsigned*)&g_bar_gen;

    // ---------------- phase 0: int16 quantization + gathers + init ----------------
    // encoder Whh -> int16, per-row scale (warp per row)
    for (int r = gw; r < 8192; r += TW) {
        const float4* src = (const float4*)(enc_Whh + (size_t)r * 2048);
        float m = 0.f;
        for (int i = lane; i < 512; i += 32) {
            float4 v = __ldg(src + i);
            m = fmaxf(m, fmaxf(fmaxf(fabsf(v.x), fabsf(v.y)), fmaxf(fabsf(v.z), fabsf(v.w))));
        }
        m = wredmax(m);
        if (m == 0.f) m = 1.f;
        float inv = 32767.0f / m;
        if (lane == 0) g_enc_scale[r] = m / 32767.0f;
        uint2* dst = (uint2*)(g_Whh_q + (size_t)r * 2048);
        for (int i = lane; i < 512; i += 32) {
            float4 v = __ldg(src + i);
            uint2 o2;
            o2.x = pack2q(v.x, v.y, inv);
            o2.y = pack2q(v.z, v.w, inv);
            dst[i] = o2;
        }
    }
    // decoder Wsum = Wih + Whh -> int16, per-row scale (8192 row-tasks, d = r>>12)
    for (int r = gw; r < 8192; r += TW) {
        const int d = r >> 12, row = r & 4095;
        const float4* A = (const float4*)((d ? recr_Wih : recf_Wih) + (size_t)row * 1024);
        const float4* B = (const float4*)((d ? recr_Whh : recf_Whh) + (size_t)row * 1024);
        float m = 0.f;
        for (int i = lane; i < 256; i += 32) {
            float4 a = __ldg(A + i), b = __ldg(B + i);
            float sx = a.x + b.x, sy = a.y + b.y, sz = a.z + b.z, sw = a.w + b.w;
            m = fmaxf(m, fmaxf(fmaxf(fabsf(sx), fabsf(sy)), fmaxf(fabsf(sz), fabsf(sw))));
        }
        m = wredmax(m);
        if (m == 0.f) m = 1.f;
        float inv = 32767.0f / m;
        if (lane == 0) (d ? g_dsc_r : g_dsc_f)[row] = m / 32767.0f;
        uint2* dst = (uint2*)((d ? g_Wsum_r_q : g_Wsum_f_q) + (size_t)row * 1024);
        for (int i = lane; i < 256; i += 32) {
            float4 a = __ldg(A + i), b = __ldg(B + i);
            uint2 o2;
            o2.x = pack2q(a.x + b.x, a.y + b.y, inv);
            o2.y = pack2q(a.z + b.z, a.w + b.w, inv);
            dst[i] = o2;
        }
    }
    for (int i = gtid; i < 4096; i += gsz) {
        g_bsum_f[i] = recf_bih[i] + recf_bhh[i];
        g_bsum_r[i] = recr_bih[i] + recr_bhh[i];
    }
    for (int i = gtid; i < 8192; i += gsz) g_enc_bsum[i] = enc_bih[i] + enc_bhh[i];
    for (int i = gtid; i < 256 * 1024; i += gsz) {
        int t = i >> 10, k = i & 1023;
        float v = emb[(x[t] << 10) + k];
        out_embf[i] = v;
        out_embr[((255 - t) << 10) + k] = v;
    }
    for (int k = gtid; k < 1024; k += gsz) {
        float e0 = emb[k], e1 = emb[1024 + k];
        out_recf[k] = e1;               // rec_f row 0   = end (emb[B_IDX=1])
        out_recf[255 * 1024 + k] = e0;  // rec_f row 255 = start (emb[X_IDX=0])
        out_recr[k] = e0;               // rec_r row 0   = end (emb[0])
        out_recr[255 * 1024 + k] = e1;  // rec_r row 255 = start (emb[1])
    }
    for (int k = gtid; k < 64; k += gsz) {
        float v = emb_Vg[(Vg[0] << 6) + k];
        g_h0f[k] = v; g_h0r[k] = v; out[k] = v; out[640 + k] = v;
        float jv = emb_Jg[(Jg[0] << 6) + k];
        g_h0f[576 + k] = jv; g_h0r[576 + k] = jv;
        out[576 + k] = jv; out[640 + 576 + k] = jv;
    }
    for (int k = gtid; k < 2048; k += gsz) { g_hf[0][k] = 0.f; g_hr[0][k] = 0.f; }
    bar++; gsync(bar);

    // ---------------- phase 0b: gates_x GEMM  (enc_Wih @ emb_f + bsum, all 256 t) ----
    // 128 blocks: tc = t-chunk of 8 timesteps (32 chunks), rg = 2048-row group (4 groups)
    if (blockIdx.x < 128) {
        const int tc = blockIdx.x & 31;
        const int rg = blockIdx.x >> 5;
        {   // stage x[8][1024] fp32 into smem
            const float4* src = (const float4*)(out_embf + (size_t)tc * 8 * 1024);
            float4* d4 = (float4*)sbuf;
            for (int i = tid; i < 2048; i += NTHR) d4[i] = __ldcg(src + i);
        }
        __syncthreads();
        const float4* SX = (const float4*)sbuf;
        const int rend = rg * 2048 + 2048;
        for (int r = rg * 2048 + wlocal; r < rend; r += NW) {
            const float4* W = (const float4*)(enc_Wih + (size_t)r * 1024);
            float a0 = 0.f, a1 = 0.f, a2 = 0.f, a3 = 0.f;
            float a4 = 0.f, a5 = 0.f, a6 = 0.f, a7 = 0.f;
#pragma unroll 4
            for (int i = lane; i < 256; i += 32) {
                float4 w = __ldg(W + i);
                a0 += dot4(w, SX[i]);        a1 += dot4(w, SX[256 + i]);
                a2 += dot4(w, SX[512 + i]);  a3 += dot4(w, SX[768 + i]);
                a4 += dot4(w, SX[1024 + i]); a5 += dot4(w, SX[1280 + i]);
                a6 += dot4(w, SX[1536 + i]); a7 += dot4(w, SX[1792 + i]);
            }
            a0 = wredsum(a0); a1 = wredsum(a1); a2 = wredsum(a2); a3 = wredsum(a3);
            a4 = wredsum(a4); a5 = wredsum(a5); a6 = wredsum(a6); a7 = wredsum(a7);
            if (lane == 0) {
                float b = g_enc_bsum[r];
                float* gp = g_gatesx + r;
                gp[(size_t)(tc * 8 + 0) * 8192] = a0 + b;
                gp[(size_t)(tc * 8 + 1) * 8192] = a1 + b;
                gp[(size_t)(tc * 8 + 2) * 8192] = a2 + b;
                gp[(size_t)(tc * 8 + 3) * 8192] = a3 + b;
                gp[(size_t)(tc * 8 + 4) * 8192] = a4 + b;
                gp[(size_t)(tc * 8 + 5) * 8192] = a5 + b;
                gp[(size_t)(tc * 8 + 6) * 8192] = a6 + b;
                gp[(size_t)(tc * 8 + 7) * 8192] = a7 + b;
            }
        }
    }
    bar++; gsync(bar);

    // ---------------- encoder: 256 steps, Whh-only (int16), split-K 2 warps/unit ----
    const bool evalid = (u < 2048);
    float ec = 0.f;   // lane0 (half0): fwd cell; lane1 (half0): rev cell
    float esc0 = 0.f, esc1 = 0.f, esc2 = 0.f, esc3 = 0.f;
    const uint4 *V0 = 0, *V1 = 0, *V2 = 0, *V3 = 0;
    if (evalid) {
        esc0 = __ldg(&g_enc_scale[u]);
        esc1 = __ldg(&g_enc_scale[u + 2048]);
        esc2 = __ldg(&g_enc_scale[u + 4096]);
        esc3 = __ldg(&g_enc_scale[u + 6144]);
        V0 = (const uint4*)(g_Whh_q + (size_t)u * 2048) + half * 128;
        V1 = (const uint4*)(g_Whh_q + (size_t)(u + 2048) * 2048) + half * 128;
        V2 = (const uint4*)(g_Whh_q + (size_t)(u + 4096) * 2048) + half * 128;
        V3 = (const uint4*)(g_Whh_q + (size_t)(u + 6144) * 2048) + half * 128;
    }
#pragma unroll 1
    for (int t = 0; t < 256; t++) {
        stage4(sbuf, g_hf[t & 1], 512);          // hf at floats [0,2048)
        stage4(sbuf + 2048, g_hr[t & 1], 512);   // hr at floats [2048,4096)
        __syncthreads();
        float af0 = 0.f, af1 = 0.f, af2 = 0.f, af3 = 0.f;
        float ar0 = 0.f, ar1 = 0.f, ar2 = 0.f, ar3 = 0.f;
        float gx0 = 0.f, gx1 = 0.f, gx2 = 0.f, gx3 = 0.f;
        if (evalid) {
            if (half == 0 && lane < 2) {  // prefetch gates_x early (off the dot chain)
                const float* gx = g_gatesx + (size_t)(lane == 0 ? t : 255 - t) * 8192 + u;
                gx0 = __ldg(gx); gx1 = __ldg(gx + 2048);
                gx2 = __ldg(gx + 4096); gx3 = __ldg(gx + 6144);
            }
            const float4* HF = (const float4*)sbuf + half * 256;
            const float4* HR = (const float4*)(sbuf + 2048) + half * 256;
#pragma unroll 2
            for (int i = lane; i < 128; i += 32) {
                float4 f0 = HF[2 * i], f1 = HF[2 * i + 1];
                float4 r0 = HR[2 * i], r1 = HR[2 * i + 1];
                acc8x2q(af0, ar0, __ldg(V0 + i), f0, f1, r0, r1);
                acc8x2q(af1, ar1, __ldg(V1 + i), f0, f1, r0, r1);
                acc8x2q(af2, ar2, __ldg(V2 + i), f0, f1, r0, r1);
                acc8x2q(af3, ar3, __ldg(V3 + i), f0, f1, r0, r1);
            }
            af0 = wredsum(af0); af1 = wredsum(af1); af2 = wredsum(af2); af3 = wredsum(af3);
            ar0 = wredsum(ar0); ar1 = wredsum(ar1); ar2 = wredsum(ar2); ar3 = wredsum(ar3);
            if (half == 1 && lane == 0) {
                spar[uL][0] = af0; spar[uL][1] = af1; spar[uL][2] = af2; spar[uL][3] = af3;
                spar[uL][4] = ar0; spar[uL][5] = ar1; spar[uL][6] = ar2; spar[uL][7] = ar3;
            }
        }
        __syncthreads();
        if (evalid && half == 0 && lane < 2) {
            // lane0: fwd direction (af*, gx@t); lane1: rev direction (ar*, gx@255-t)
            float s0 = (lane == 0 ? af0 : ar0) + spar[uL][lane * 4 + 0];
            float s1 = (lane == 0 ? af1 : ar1) + spar[uL][lane * 4 + 1];
            float s2 = (lane == 0 ? af2 : ar2) + spar[uL][lane * 4 + 2];
            float s3 = (lane == 0 ? af3 : ar3) + spar[uL][lane * 4 + 3];
            float ig = sigmoidf_(s0 * esc0 + gx0);
            float fg = sigmoidf_(s1 * esc1 + gx1);
            float gg = tanhf(s2 * esc2 + gx2);
            float og = sigmoidf_(s3 * esc3 + gx3);
            ec = fg * ec + ig * gg;
            float hn = og * tanhf(ec);
            (lane == 0 ? g_hf : g_hr)[(t + 1) & 1][u] = hn;
        }
        bar++; gsync(bar);
    }

    // ---------------- glue phase 1: cls + lat_f + lat_r ----------------
    stage4(sbuf, g_hf[0], 512);         // hf at [0,2048)
    stage4(sbuf + 2048, g_hr[0], 512);  // hr at [2048,4096) -> concat layout
    __syncthreads();
    if (gw < 512) {
        int row = gw;
        const float4* W = (const float4*)(cls_W + (size_t)row * 4096);
        const float4* S = (const float4*)sbuf;
        float acc = 0.f;
        for (int i = lane; i < 1024; i += 32) acc += dot4(__ldg(W + i), S[i]);
        acc = wredsum(acc);
        if (lane == 0) g_common[row] = tanhf(acc + cls_b[row]);
    } else if (gw < 1024) {
        int row = gw - 512;
        const float4* W = (const float4*)(latf_W + (size_t)row * 2048);
        const float4* S = (const float4*)sbuf;
        float acc = 0.f;
        for (int i = lane; i < 512; i += 32) acc += dot4(__ldg(W + i), S[i]);
        acc = wredsum(acc);
        if (lane == 0) { float v = acc + latf_b[row]; g_h0f[64 + row] = v; out[64 + row] = v; }
    } else if (gw < 1536) {
        int row = gw - 1024;
        const float4* W = (const float4*)(latr_W + (size_t)row * 2048);
        const float4* S = (const float4*)(sbuf + 2048);
        float acc = 0.f;
        for (int i = lane; i < 512; i += 32) acc += dot4(__ldg(W + i), S[i]);
        acc = wredsum(acc);
        if (lane == 0) { float v = acc + latr_b[row]; g_h0r[64 + row] = v; out[640 + 64 + row] = v; }
    }
    bar++; gsync(bar);

    // ---------------- glue phase 2: mix ----------------
    stage4(sbuf, g_common, 128);
    __syncthreads();
    if (gw < 384) {
        int row = gw;
        const float4* W = (const float4*)(mix_W + (size_t)row * 512);
        const float4* S = (const float4*)sbuf;
        float acc = 0.f;
        for (int i = lane; i < 128; i += 32) acc += dot4(__ldg(W + i), S[i]);
        acc = wredsum(acc);
        if (lane == 0) { float v = acc + mix_b[row]; g_h0f[640 + row] = v; g_h0r[640 + row] = v; }
    }
    bar++; gsync(bar);

    // ---------------- decoders: 254 steps, split-K 2 warps/task ----------
    const int d = (u >= 1024) ? 1 : 0;
    const int dj = u - (d << 10);
    float dcc = 0.f;  // lives on half0/lane0 only
    float dsc0 = 0.f, dsc1 = 0.f, dsc2 = 0.f, dsc3 = 0.f;
    float bs0 = 0.f, bs1 = 0.f, bs2 = 0.f, bs3 = 0.f;
    const uint4 *P0 = 0, *P1 = 0, *P2 = 0, *P3 = 0;
    if (evalid) {
        const float* dsc = d ? g_dsc_r : g_dsc_f;
        dsc0 = __ldg(&dsc[dj]);        dsc1 = __ldg(&dsc[dj + 1024]);
        dsc2 = __ldg(&dsc[dj + 2048]); dsc3 = __ldg(&dsc[dj + 3072]);
        const float* bs = d ? g_bsum_r : g_bsum_f;
        bs0 = __ldg(&bs[dj]);        bs1 = __ldg(&bs[dj + 1024]);
        bs2 = __ldg(&bs[dj + 2048]); bs3 = __ldg(&bs[dj + 3072]);
        const short* W = d ? g_Wsum_r_q : g_Wsum_f_q;
        P0 = (const uint4*)(W + (size_t)dj * 1024) + half * 64;
        P1 = (const uint4*)(W + (size_t)(dj + 1024) * 1024) + half * 64;
        P2 = (const uint4*)(W + (size_t)(dj + 2048) * 1024) + half * 64;
        P3 = (const uint4*)(W + (size_t)(dj + 3072) * 1024) + half * 64;
    }
#pragma unroll 1
    for (int s = 1; s <= 254; s++) {
        if (s == 1) {
            stage4(sbuf, emb, 256);                 // start_f = emb[0]
            stage4(sbuf + 1024, g_h0f, 256);
            stage4(sbuf + 2048, emb + 1024, 256);   // start_r = emb[1]
            stage4(sbuf + 3072, g_h0r, 256);
        } else {
            stage4(sbuf, g_dhf[s & 1], 256);
            stage4(sbuf + 2048, g_dhr[s & 1], 256);
        }
        __syncthreads();
        float a0 = 0.f, a1 = 0.f, a2 = 0.f, a3 = 0.f;
        if (evalid) {
            if (s == 1) {
                // first step: prev != h, use original fp32 weights (one-time cost)
                const float4* X = (const float4*)(sbuf + (d << 11)) + half * 128;
                const float* Wih = d ? recr_Wih : recf_Wih;
                const float* Whh = d ? recr_Whh : recf_Whh;
                const float4* R0 = (const float4*)(Wih + (size_t)dj * 1024) + half * 128;
                const float4* R1 = (const float4*)(Wih + (size_t)(dj + 1024) * 1024) + half * 128;
                const float4* R2 = (const float4*)(Wih + (size_t)(dj + 2048) * 1024) + half * 128;
                const float4* R3 = (const float4*)(Wih + (size_t)(dj + 3072) * 1024) + half * 128;
#pragma unroll 2
                for (int i = lane; i < 128; i += 32) {
                    float4 xv = X[i], w;
                    w = __ldg(R0 + i); a0 += dot4(w, xv);
                    w = __ldg(R1 + i); a1 += dot4(w, xv);
                    w = __ldg(R2 + i); a2 += dot4(w, xv);
                    w = __ldg(R3 + i); a3 += dot4(w, xv);
                }
                const float4* H = (const float4*)(sbuf + (d << 11) + 1024) + half * 128;
                const float4* Q0 = (const float4*)(Whh + (size_t)dj * 1024) + half * 128;
                const float4* Q1 = (const float4*)(Whh + (size_t)(dj + 1024) * 1024) + half * 128;
                const float4* Q2 = (const float4*)(Whh + (size_t)(dj + 2048) * 1024) + half * 128;
                const float4* Q3 = (const float4*)(Whh + (size_t)(dj + 3072) * 1024) + half * 128;
#pragma unroll 2
                for (int i = lane; i < 128; i += 32) {
                    float4 hv = H[i], w;
                    w = __ldg(Q0 + i); a0 += dot4(w, hv);
                    w = __ldg(Q1 + i); a1 += dot4(w, hv);
                    w = __ldg(Q2 + i); a2 += dot4(w, hv);
                    w = __ldg(Q3 + i); a3 += dot4(w, hv);
                }
                if (half == 0) dcc = sbuf[(d << 11) + 1024 + dj];  // c0 = h0 value
            } else {
                const float4* X = (const float4*)(sbuf + (d << 11)) + half * 128;
#pragma unroll 2
                for (int i = lane; i < 64; i += 32) {
                    float4 x0 = X[2 * i], x1 = X[2 * i + 1];
                    a0 += dot8q(__ldg(P0 + i), x0, x1);
                    a1 += dot8q(__ldg(P1 + i), x0, x1);
                    a2 += dot8q(__ldg(P2 + i), x0, x1);
                    a3 += dot8q(__ldg(P3 + i), x0, x1);
                }
                a0 *= dsc0; a1 *= dsc1; a2 *= dsc2; a3 *= dsc3;
            }
            a0 = wredsum(a0); a1 = wredsum(a1); a2 = wredsum(a2); a3 = wredsum(a3);
            if (half == 1 && lane == 0) {
                spar[uL][0] = a0; spar[uL][1] = a1; spar[uL][2] = a2; spar[uL][3] = a3;
            }
        }
        __syncthreads();
        if (evalid && half == 0 && lane == 0) {
            a0 += spar[uL][0]; a1 += spar[uL][1]; a2 += spar[uL][2]; a3 += spar[uL][3];
            float ig = sigmoidf_(a0 + bs0);
            float fg = sigmoidf_(a1 + bs1);
            float gg = tanhf(a2 + bs2);
            float og = sigmoidf_(a3 + bs3);
            dcc = fg * dcc + ig * gg;
            float h2 = og * tanhf(dcc);
            float* dh = d ? g_dhr[(s + 1) & 1] : g_dhf[(s + 1) & 1];
            dh[dj] = h2;
            float* orow = (d ? out_recr : out_recf) + (size_t)(255 - s) * 1024;
            orow[dj] = h2;
        }
        bar++; gsync(bar);
    }
}

extern "C" void kernel_launch(void* const* d_in, const int* in_sizes, int n_in,
                              void* d_out, int out_size) {
    (void)in_sizes; (void)n_in; (void)out_size;
    ae_kernel<<<NBLK, NTHR>>>(
        (const int*)d_in[0], (const int*)d_in[1], (const int*)d_in[2],
        (const float*)d_in[3], (const float*)d_in[4], (const float*)d_in[5],
        (const float*)d_in[6], (const float*)d_in[7], (const float*)d_in[8],
        (const float*)d_in[9], (const float*)d_in[10], (const float*)d_in[11],
        (const float*)d_in[12], (const float*)d_in[13], (const float*)d_in[14],
        (const float*)d_in[15], (const float*)d_in[16], (const float*)d_in[17],
        (const float*)d_in[18], (const float*)d_in[19], (const float*)d_in[20],
        (const float*)d_in[21], (const float*)d_in[22], (const float*)d_in[23],
        (const float*)d_in[24], (const float*)d_in[25],
        (float*)d_out);
}

// round 11
// speedup vs baseline: 1.9627x; 1.0489x over previous
#include <cuda_runtime.h>

#define NBLK 148
#define NTHR 896
#define NW   (NTHR / 32)
#define TW   (NBLK * NW)
#define DSM_BYTES 229376   // 16KB staging + 13 units * 16KB encoder weights

// ---------------- static device scratch (no runtime allocation) ----------------
__device__ __align__(16) short g_Whh_q[8192 * 2048];     // encoder Whh, int16 (33.5MB)
__device__ __align__(16) short g_Wsum_f_q[4096 * 1024];  // recf Wih+Whh, int16 (8.4MB)
__device__ __align__(16) short g_Wsum_r_q[4096 * 1024];  // recr Wih+Whh, int16 (8.4MB)
__device__ __align__(16) float g_enc_scale[8192];        // per-row dequant scale
__device__ __align__(16) float g_dsc_f[4096];
__device__ __align__(16) float g_dsc_r[4096];
__device__ __align__(16) float g_gatesx[256 * 8192];     // enc_Wih@x + bias, all t (8.4MB)
__device__ __align__(16) float g_bsum_f[4096];
__device__ __align__(16) float g_bsum_r[4096];
__device__ __align__(16) float g_enc_bsum[8192];
__device__ __align__(16) float g_hf[2][2048];   // encoder fwd hidden (double buffered)
__device__ __align__(16) float g_hr[2][2048];   // encoder rev hidden
__device__ __align__(16) float g_common[512];
__device__ __align__(16) float g_h0f[1024];
__device__ __align__(16) float g_h0r[1024];
__device__ __align__(16) float g_dhf[2][1024];  // decoder f hidden
__device__ __align__(16) float g_dhr[2][1024];  // decoder r hidden
__device__ unsigned g_bar_cnt = 0;
__device__ unsigned g_bar_gen = 0;

// ---------------- grid barrier (sense via monotonically increasing gen) --------
__device__ __forceinline__ void gsync(unsigned target) {
    __syncthreads();
    if (threadIdx.x == 0) {
        __threadfence();
        unsigned a = atomicAdd(&g_bar_cnt, 1u);
        if (a == gridDim.x - 1) {
            atomicExch(&g_bar_cnt, 0u);
            __threadfence();
            atomicExch(&g_bar_gen, target);
        } else {
            volatile unsigned* p = &g_bar_gen;
            while ((int)(*p - target) < 0) { __nanosleep(32); }
        }
        __threadfence();
    }
    __syncthreads();
}

__device__ __forceinline__ float wredsum(float v) {
#pragma unroll
    for (int o = 16; o; o >>= 1) v += __shfl_xor_sync(0xffffffffu, v, o);
    return v;
}
__device__ __forceinline__ float wredmax(float v) {
#pragma unroll
    for (int o = 16; o; o >>= 1) v = fmaxf(v, __shfl_xor_sync(0xffffffffu, v, o));
    return v;
}
__device__ __forceinline__ float sigmoidf_(float v) { return 1.0f / (1.0f + __expf(-v)); }
__device__ __forceinline__ float dot4(float4 a, float4 b) {
    return a.x * b.x + a.y * b.y + a.z * b.z + a.w * b.w;
}
// stage a run of floats (multiple of 4) into shared, bypassing L1 (fresh data)
__device__ __forceinline__ void stage4(float* dst, const float* src, int n4) {
    float4* d4 = (float4*)dst;
    const float4* s4 = (const float4*)src;
    for (int i = threadIdx.x; i < n4; i += NTHR) d4[i] = __ldcg(s4 + i);
}
// int16x8 weights: dual-direction accumulate (raw integer-valued dot; scale later)
__device__ __forceinline__ void acc8x2q(float& af, float& ar, uint4 w,
                                        float4 f0, float4 f1, float4 r0, float4 r1) {
    float c0 = (float)(short)(w.x);
    float c1 = (float)((short)(w.x >> 16));
    float c2 = (float)(short)(w.y);
    float c3 = (float)((short)(w.y >> 16));
    float c4 = (float)(short)(w.z);
    float c5 = (float)((short)(w.z >> 16));
    float c6 = (float)(short)(w.w);
    float c7 = (float)((short)(w.w >> 16));
    af += c0 * f0.x + c1 * f0.y + c2 * f0.z + c3 * f0.w
        + c4 * f1.x + c5 * f1.y + c6 * f1.z + c7 * f1.w;
    ar += c0 * r0.x + c1 * r0.y + c2 * r0.z + c3 * r0.w
        + c4 * r1.x + c5 * r1.y + c6 * r1.z + c7 * r1.w;
}
__device__ __forceinline__ float dot8q(uint4 w, float4 x0, float4 x1) {
    float c0 = (float)(short)(w.x);
    float c1 = (float)((short)(w.x >> 16));
    float c2 = (float)(short)(w.y);
    float c3 = (float)((short)(w.y >> 16));
    float c4 = (float)(short)(w.z);
    float c5 = (float)((short)(w.z >> 16));
    float c6 = (float)(short)(w.w);
    float c7 = (float)((short)(w.w >> 16));
    return c0 * x0.x + c1 * x0.y + c2 * x0.z + c3 * x0.w
         + c4 * x1.x + c5 * x1.y + c6 * x1.z + c7 * x1.w;
}
__device__ __forceinline__ unsigned pack2q(float a, float b, float inv) {
    int q0 = __float2int_rn(a * inv);
    int q1 = __float2int_rn(b * inv);
    return (unsigned)(q0 & 0xffff) | ((unsigned)q1 << 16);
}

__global__ void __launch_bounds__(NTHR)
ae_kernel(const int* __restrict__ x, const int* __restrict__ Vg, const int* __restrict__ Jg,
          const float* __restrict__ emb, const float* __restrict__ emb_Vg,
          const float* __restrict__ emb_Jg,
          const float* __restrict__ enc_Wih, const float* __restrict__ enc_Whh,
          const float* __restrict__ enc_bih, const float* __restrict__ enc_bhh,
          const float* __restrict__ cls_W, const float* __restrict__ cls_b,
          const float* __restrict__ latf_W, const float* __restrict__ latf_b,
          const float* __restrict__ latr_W, const float* __restrict__ latr_b,
          const float* __restrict__ mix_W, const float* __restrict__ mix_b,
          const float* __restrict__ recf_Wih, const float* __restrict__ recf_Whh,
          const float* __restrict__ recf_bih, const float* __restrict__ recf_bhh,
          const float* __restrict__ recr_Wih, const float* __restrict__ recr_Whh,
          const float* __restrict__ recr_bih, const float* __restrict__ recr_bhh,
          float* __restrict__ out) {
    extern __shared__ __align__(16) char dsm[];
    float* sbuf = (float*)dsm;                        // [0, 16KB) staging (32KB in GEMM phase)
    short* sw16 = (short*)(dsm + 16384);              // weights region
    __shared__ __align__(16) float spar[14][8];       // split-K partials (unit-local)
    const int tid = threadIdx.x;
    const int lane = tid & 31;
    const int wlocal = tid >> 5;
    const int gw = blockIdx.x * NW + wlocal;
    const int gtid = blockIdx.x * NTHR + tid;
    const int gsz = NBLK * NTHR;

    // split-K pairing: two consecutive warps serve one unit/task
    const int uL = wlocal >> 1;                     // unit index within block (0..13)
    const int half = wlocal & 1;                    // K-half this warp covers
    const int u = blockIdx.x * 14 + uL;             // global unit/task id

    float* out_recf = out + 1280;
    float* out_recr = out + 1280 + 262144;
    float* out_embf = out + 1280 + 2 * 262144;
    float* out_embr = out + 1280 + 3 * 262144;

    // barrier base: graph replays leave g_bar_gen at the previous total.
    unsigned bar = *(volatile unsigned*)&g_bar_gen;

    // ---------------- phase 0: int16 quantization + gathers + init ----------------
    // encoder Whh -> int16, per-row scale (warp per row)
    for (int r = gw; r < 8192; r += TW) {
        const float4* src = (const float4*)(enc_Whh + (size_t)r * 2048);
        float m = 0.f;
        for (int i = lane; i < 512; i += 32) {
            float4 v = __ldg(src + i);
            m = fmaxf(m, fmaxf(fmaxf(fabsf(v.x), fabsf(v.y)), fmaxf(fabsf(v.z), fabsf(v.w))));
        }
        m = wredmax(m);
        if (m == 0.f) m = 1.f;
        float inv = 32767.0f / m;
        if (lane == 0) g_enc_scale[r] = m / 32767.0f;
        uint2* dst = (uint2*)(g_Whh_q + (size_t)r * 2048);
        for (int i = lane; i < 512; i += 32) {
            float4 v = __ldg(src + i);
            uint2 o2;
            o2.x = pack2q(v.x, v.y, inv);
            o2.y = pack2q(v.z, v.w, inv);
            dst[i] = o2;
        }
    }
    // decoder Wsum = Wih + Whh -> int16, per-row scale (8192 row-tasks, d = r>>12)
    for (int r = gw; r < 8192; r += TW) {
        const int d = r >> 12, row = r & 4095;
        const float4* A = (const float4*)((d ? recr_Wih : recf_Wih) + (size_t)row * 1024);
        const float4* B = (const float4*)((d ? recr_Whh : recf_Whh) + (size_t)row * 1024);
        float m = 0.f;
        for (int i = lane; i < 256; i += 32) {
            float4 a = __ldg(A + i), b = __ldg(B + i);
            float sx = a.x + b.x, sy = a.y + b.y, sz = a.z + b.z, sw = a.w + b.w;
            m = fmaxf(m, fmaxf(fmaxf(fabsf(sx), fabsf(sy)), fmaxf(fabsf(sz), fabsf(sw))));
        }
        m = wredmax(m);
        if (m == 0.f) m = 1.f;
        float inv = 32767.0f / m;
        if (lane == 0) (d ? g_dsc_r : g_dsc_f)[row] = m / 32767.0f;
        uint2* dst = (uint2*)((d ? g_Wsum_r_q : g_Wsum_f_q) + (size_t)row * 1024);
        for (int i = lane; i < 256; i += 32) {
            float4 a = __ldg(A + i), b = __ldg(B + i);
            uint2 o2;
            o2.x = pack2q(a.x + b.x, a.y + b.y, inv);
            o2.y = pack2q(a.z + b.z, a.w + b.w, inv);
            dst[i] = o2;
        }
    }
    for (int i = gtid; i < 4096; i += gsz) {
        g_bsum_f[i] = recf_bih[i] + recf_bhh[i];
        g_bsum_r[i] = recr_bih[i] + recr_bhh[i];
    }
    for (int i = gtid; i < 8192; i += gsz) g_enc_bsum[i] = enc_bih[i] + enc_bhh[i];
    for (int i = gtid; i < 256 * 1024; i += gsz) {
        int t = i >> 10, k = i & 1023;
        float v = emb[(x[t] << 10) + k];
        out_embf[i] = v;
        out_embr[((255 - t) << 10) + k] = v;
    }
    for (int k = gtid; k < 1024; k += gsz) {
        float e0 = emb[k], e1 = emb[1024 + k];
        out_recf[k] = e1;               // rec_f row 0   = end (emb[B_IDX=1])
        out_recf[255 * 1024 + k] = e0;  // rec_f row 255 = start (emb[X_IDX=0])
        out_recr[k] = e0;               // rec_r row 0   = end (emb[0])
        out_recr[255 * 1024 + k] = e1;  // rec_r row 255 = start (emb[1])
    }
    for (int k = gtid; k < 64; k += gsz) {
        float v = emb_Vg[(Vg[0] << 6) + k];
        g_h0f[k] = v; g_h0r[k] = v; out[k] = v; out[640 + k] = v;
        float jv = emb_Jg[(Jg[0] << 6) + k];
        g_h0f[576 + k] = jv; g_h0r[576 + k] = jv;
        out[576 + k] = jv; out[640 + 576 + k] = jv;
    }
    for (int k = gtid; k < 2048; k += gsz) { g_hf[0][k] = 0.f; g_hr[0][k] = 0.f; }
    bar++; gsync(bar);

    // ---------------- phase 0b: gates_x GEMM  (enc_Wih @ emb_f + bsum, all 256 t) ----
    // 128 blocks: tc = t-chunk of 8 timesteps (32 chunks), rg = 2048-row group (4 groups)
    if (blockIdx.x < 128) {
        const int tc = blockIdx.x & 31;
        const int rg = blockIdx.x >> 5;
        {   // stage x[8][1024] fp32 into smem (32KB at base; overwritten later by preload)
            const float4* src = (const float4*)(out_embf + (size_t)tc * 8 * 1024);
            float4* d4 = (float4*)sbuf;
            for (int i = tid; i < 2048; i += NTHR) d4[i] = __ldcg(src + i);
        }
        __syncthreads();
        const float4* SX = (const float4*)sbuf;
        const int rend = rg * 2048 + 2048;
        for (int r = rg * 2048 + wlocal; r < rend; r += NW) {
            const float4* W = (const float4*)(enc_Wih + (size_t)r * 1024);
            float a0 = 0.f, a1 = 0.f, a2 = 0.f, a3 = 0.f;
            float a4 = 0.f, a5 = 0.f, a6 = 0.f, a7 = 0.f;
#pragma unroll 4
            for (int i = lane; i < 256; i += 32) {
                float4 w = __ldg(W + i);
                a0 += dot4(w, SX[i]);        a1 += dot4(w, SX[256 + i]);
                a2 += dot4(w, SX[512 + i]);  a3 += dot4(w, SX[768 + i]);
                a4 += dot4(w, SX[1024 + i]); a5 += dot4(w, SX[1280 + i]);
                a6 += dot4(w, SX[1536 + i]); a7 += dot4(w, SX[1792 + i]);
            }
            a0 = wredsum(a0); a1 = wredsum(a1); a2 = wredsum(a2); a3 = wredsum(a3);
            a4 = wredsum(a4); a5 = wredsum(a5); a6 = wredsum(a6); a7 = wredsum(a7);
            if (lane == 0) {
                float b = g_enc_bsum[r];
                float* gp = g_gatesx + r;
                gp[(size_t)(tc * 8 + 0) * 8192] = a0 + b;
                gp[(size_t)(tc * 8 + 1) * 8192] = a1 + b;
                gp[(size_t)(tc * 8 + 2) * 8192] = a2 + b;
                gp[(size_t)(tc * 8 + 3) * 8192] = a3 + b;
                gp[(size_t)(tc * 8 + 4) * 8192] = a4 + b;
                gp[(size_t)(tc * 8 + 5) * 8192] = a5 + b;
                gp[(size_t)(tc * 8 + 6) * 8192] = a6 + b;
                gp[(size_t)(tc * 8 + 7) * 8192] = a7 + b;
            }
        }
    }
    __syncthreads();   // GEMM smem reads done before preload overwrites the region

    // ---------------- preload encoder weights for units 0..12 into smem ----------
    // layout: row = uL*4 + gate, each row 2048 int16 (256 uint4), halves contiguous
    {
        uint4* dst = (uint4*)sw16;
        const int ubase = blockIdx.x * 14;
        for (int idx = tid; idx < 13 * 4 * 256; idx += NTHR) {
            int row = idx >> 8;          // 0..51
            int r4  = idx & 255;
            int unit = row >> 2, gate = row & 3;
            int gu = ubase + unit;
            if (gu < 2048) {
                const uint4* src = (const uint4*)(g_Whh_q + ((size_t)gu + (size_t)gate * 2048) * 2048) + r4;
                dst[row * 256 + r4] = __ldcg(src);
            }
        }
    }
    bar++; gsync(bar);

    // ---------------- encoder: 256 steps, Whh-only (int16), split-K 2 warps/unit ----
    const bool evalid = (u < 2048);
    float ec = 0.f;   // lane0 (half0): fwd cell; lane1 (half0): rev cell
    float esc0 = 0.f, esc1 = 0.f, esc2 = 0.f, esc3 = 0.f;
    if (evalid) {
        esc0 = __ldg(&g_enc_scale[u]);
        esc1 = __ldg(&g_enc_scale[u + 2048]);
        esc2 = __ldg(&g_enc_scale[u + 4096]);
        esc3 = __ldg(&g_enc_scale[u + 6144]);
    }
#pragma unroll 1
    for (int t = 0; t < 256; t++) {
        stage4(sbuf, g_hf[t & 1], 512);          // hf at floats [0,2048)
        stage4(sbuf + 2048, g_hr[t & 1], 512);   // hr at floats [2048,4096)
        __syncthreads();
        float af0 = 0.f, af1 = 0.f, af2 = 0.f, af3 = 0.f;
        float ar0 = 0.f, ar1 = 0.f, ar2 = 0.f, ar3 = 0.f;
        float gx0 = 0.f, gx1 = 0.f, gx2 = 0.f, gx3 = 0.f;
        if (evalid) {
            if (half == 0 && lane < 2) {  // prefetch gates_x early (off the dot chain)
                const float* gx = g_gatesx + (size_t)(lane == 0 ? t : 255 - t) * 8192 + u;
                gx0 = __ldg(gx); gx1 = __ldg(gx + 2048);
                gx2 = __ldg(gx + 4096); gx3 = __ldg(gx + 6144);
            }
            const float4* HF = (const float4*)sbuf + half * 256;
            const float4* HR = (const float4*)(sbuf + 2048) + half * 256;
            if (uL < 13) {
                // weights resident in shared memory (LDS)
                const uint4* S0 = (const uint4*)sw16 + (uL * 4) * 256 + half * 128;
                const uint4* S1 = S0 + 256;
                const uint4* S2 = S0 + 512;
                const uint4* S3 = S0 + 768;
#pragma unroll 2
                for (int i = lane; i < 128; i += 32) {
                    float4 f0 = HF[2 * i], f1 = HF[2 * i + 1];
                    float4 r0 = HR[2 * i], r1 = HR[2 * i + 1];
                    acc8x2q(af0, ar0, S0[i], f0, f1, r0, r1);
                    acc8x2q(af1, ar1, S1[i], f0, f1, r0, r1);
                    acc8x2q(af2, ar2, S2[i], f0, f1, r0, r1);
                    acc8x2q(af3, ar3, S3[i], f0, f1, r0, r1);
                }
            } else {
                // 14th unit streams from L2 (16KB/block/step — negligible traffic)
                const uint4* V0 = (const uint4*)(g_Whh_q + (size_t)u * 2048) + half * 128;
                const uint4* V1 = (const uint4*)(g_Whh_q + (size_t)(u + 2048) * 2048) + half * 128;
                const uint4* V2 = (const uint4*)(g_Whh_q + (size_t)(u + 4096) * 2048) + half * 128;
                const uint4* V3 = (const uint4*)(g_Whh_q + (size_t)(u + 6144) * 2048) + half * 128;
#pragma unroll 2
                for (int i = lane; i < 128; i += 32) {
                    float4 f0 = HF[2 * i], f1 = HF[2 * i + 1];
                    float4 r0 = HR[2 * i], r1 = HR[2 * i + 1];
                    acc8x2q(af0, ar0, __ldg(V0 + i), f0, f1, r0, r1);
                    acc8x2q(af1, ar1, __ldg(V1 + i), f0, f1, r0, r1);
                    acc8x2q(af2, ar2, __ldg(V2 + i), f0, f1, r0, r1);
                    acc8x2q(af3, ar3, __ldg(V3 + i), f0, f1, r0, r1);
                }
            }
            af0 = wredsum(af0); af1 = wredsum(af1); af2 = wredsum(af2); af3 = wredsum(af3);
            ar0 = wredsum(ar0); ar1 = wredsum(ar1); ar2 = wredsum(ar2); ar3 = wredsum(ar3);
            if (half == 1 && lane == 0) {
                spar[uL][0] = af0; spar[uL][1] = af1; spar[uL][2] = af2; spar[uL][3] = af3;
                spar[uL][4] = ar0; spar[uL][5] = ar1; spar[uL][6] = ar2; spar[uL][7] = ar3;
            }
        }
        __syncthreads();
        if (evalid && half == 0 && lane < 2) {
            // lane0: fwd direction (af*, gx@t); lane1: rev direction (ar*, gx@255-t)
            float s0 = (lane == 0 ? af0 : ar0) + spar[uL][lane * 4 + 0];
            float s1 = (lane == 0 ? af1 : ar1) + spar[uL][lane * 4 + 1];
            float s2 = (lane == 0 ? af2 : ar2) + spar[uL][lane * 4 + 2];
            float s3 = (lane == 0 ? af3 : ar3) + spar[uL][lane * 4 + 3];
            float ig = sigmoidf_(s0 * esc0 + gx0);
            float fg = sigmoidf_(s1 * esc1 + gx1);
            float gg = tanhf(s2 * esc2 + gx2);
            float og = sigmoidf_(s3 * esc3 + gx3);
            ec = fg * ec + ig * gg;
            float hn = og * tanhf(ec);
            (lane == 0 ? g_hf : g_hr)[(t + 1) & 1][u] = hn;
        }
        bar++; gsync(bar);
    }

    // ---------------- glue phase 1: cls + lat_f + lat_r ----------------
    stage4(sbuf, g_hf[0], 512);         // hf at [0,2048)
    stage4(sbuf + 2048, g_hr[0], 512);  // hr at [2048,4096) -> concat layout
    __syncthreads();
    if (gw < 512) {
        int row = gw;
        const float4* W = (const float4*)(cls_W + (size_t)row * 4096);
        const float4* S = (const float4*)sbuf;
        float acc = 0.f;
        for (int i = lane; i < 1024; i += 32) acc += dot4(__ldg(W + i), S[i]);
        acc = wredsum(acc);
        if (lane == 0) g_common[row] = tanhf(acc + cls_b[row]);
    } else if (gw < 1024) {
        int row = gw - 512;
        const float4* W = (const float4*)(latf_W + (size_t)row * 2048);
        const float4* S = (const float4*)sbuf;
        float acc = 0.f;
        for (int i = lane; i < 512; i += 32) acc += dot4(__ldg(W + i), S[i]);
        acc = wredsum(acc);
        if (lane == 0) { float v = acc + latf_b[row]; g_h0f[64 + row] = v; out[64 + row] = v; }
    } else if (gw < 1536) {
        int row = gw - 1024;
        const float4* W = (const float4*)(latr_W + (size_t)row * 2048);
        const float4* S = (const float4*)(sbuf + 2048);
        float acc = 0.f;
        for (int i = lane; i < 512; i += 32) acc += dot4(__ldg(W + i), S[i]);
        acc = wredsum(acc);
        if (lane == 0) { float v = acc + latr_b[row]; g_h0r[64 + row] = v; out[640 + 64 + row] = v; }
    }
    bar++; gsync(bar);

    // ---------------- glue phase 2: mix ----------------
    stage4(sbuf, g_common, 128);
    __syncthreads();
    if (gw < 384) {
        int row = gw;
        const float4* W = (const float4*)(mix_W + (size_t)row * 512);
        const float4* S = (const float4*)sbuf;
        float acc = 0.f;
        for (int i = lane; i < 128; i += 32) acc += dot4(__ldg(W + i), S[i]);
        acc = wredsum(acc);
        if (lane == 0) { float v = acc + mix_b[row]; g_h0f[640 + row] = v; g_h0r[640 + row] = v; }
    }
    bar++; gsync(bar);

    // ---------------- preload decoder weights (all 14 tasks) into smem ----------
    // layout: row = uL*4 + gate, each row 1024 int16 (128 uint4)
    {
        uint4* dst = (uint4*)sw16;
        const int ubase = blockIdx.x * 14;
        for (int idx = tid; idx < 14 * 4 * 128; idx += NTHR) {
            int row = idx >> 7;          // 0..55
            int r4  = idx & 127;
            int task = row >> 2, gate = row & 3;
            int gu = ubase + task;
            if (gu < 2048) {
                int dd = gu >> 10, dj2 = gu & 1023;
                const short* W = dd ? g_Wsum_r_q : g_Wsum_f_q;
                const uint4* src = (const uint4*)(W + ((size_t)dj2 + (size_t)gate * 1024) * 1024) + r4;
                dst[row * 128 + r4] = __ldcg(src);
            }
        }
    }

    // ---------------- decoders: 254 steps, split-K 2 warps/task ----------
    const int d = (u >= 1024) ? 1 : 0;
    const int dj = u - (d << 10);
    float dcc = 0.f;  // lives on half0/lane0 only
    float dsc0 = 0.f, dsc1 = 0.f, dsc2 = 0.f, dsc3 = 0.f;
    float bs0 = 0.f, bs1 = 0.f, bs2 = 0.f, bs3 = 0.f;
    if (evalid) {
        const float* dsc = d ? g_dsc_r : g_dsc_f;
        dsc0 = __ldg(&dsc[dj]);        dsc1 = __ldg(&dsc[dj + 1024]);
        dsc2 = __ldg(&dsc[dj + 2048]); dsc3 = __ldg(&dsc[dj + 3072]);
        const float* bs = d ? g_bsum_r : g_bsum_f;
        bs0 = __ldg(&bs[dj]);        bs1 = __ldg(&bs[dj + 1024]);
        bs2 = __ldg(&bs[dj + 2048]); bs3 = __ldg(&bs[dj + 3072]);
    }
    const uint4* D0 = (const uint4*)sw16 + (uL * 4) * 128 + half * 64;
    const uint4* D1 = D0 + 128;
    const uint4* D2 = D0 + 256;
    const uint4* D3 = D0 + 384;
#pragma unroll 1
    for (int s = 1; s <= 254; s++) {
        if (s == 1) {
            stage4(sbuf, emb, 256);                 // start_f = emb[0]
            stage4(sbuf + 1024, g_h0f, 256);
            stage4(sbuf + 2048, emb + 1024, 256);   // start_r = emb[1]
            stage4(sbuf + 3072, g_h0r, 256);
        } else {
            stage4(sbuf, g_dhf[s & 1], 256);
            stage4(sbuf + 2048, g_dhr[s & 1], 256);
        }
        __syncthreads();
        float a0 = 0.f, a1 = 0.f, a2 = 0.f, a3 = 0.f;
        if (evalid) {
            if (s == 1) {
                // first step: prev != h, use original fp32 weights (one-time cost)
                const float4* X = (const float4*)(sbuf + (d << 11)) + half * 128;
                const float* Wih = d ? recr_Wih : recf_Wih;
                const float* Whh = d ? recr_Whh : recf_Whh;
                const float4* R0 = (const float4*)(Wih + (size_t)dj * 1024) + half * 128;
                const float4* R1 = (const float4*)(Wih + (size_t)(dj + 1024) * 1024) + half * 128;
                const float4* R2 = (const float4*)(Wih + (size_t)(dj + 2048) * 1024) + half * 128;
                const float4* R3 = (const float4*)(Wih + (size_t)(dj + 3072) * 1024) + half * 128;
#pragma unroll 2
                for (int i = lane; i < 128; i += 32) {
                    float4 xv = X[i], w;
                    w = __ldg(R0 + i); a0 += dot4(w, xv);
                    w = __ldg(R1 + i); a1 += dot4(w, xv);
                    w = __ldg(R2 + i); a2 += dot4(w, xv);
                    w = __ldg(R3 + i); a3 += dot4(w, xv);
                }
                const float4* H = (const float4*)(sbuf + (d << 11) + 1024) + half * 128;
                const float4* Q0 = (const float4*)(Whh + (size_t)dj * 1024) + half * 128;
                const float4* Q1 = (const float4*)(Whh + (size_t)(dj + 1024) * 1024) + half * 128;
                const float4* Q2 = (const float4*)(Whh + (size_t)(dj + 2048) * 1024) + half * 128;
                const float4* Q3 = (const float4*)(Whh + (size_t)(dj + 3072) * 1024) + half * 128;
#pragma unroll 2
                for (int i = lane; i < 128; i += 32) {
                    float4 hv = H[i], w;
                    w = __ldg(Q0 + i); a0 += dot4(w, hv);
                    w = __ldg(Q1 + i); a1 += dot4(w, hv);
                    w = __ldg(Q2 + i); a2 += dot4(w, hv);
                    w = __ldg(Q3 + i); a3 += dot4(w, hv);
                }
                if (half == 0) dcc = sbuf[(d << 11) + 1024 + dj];  // c0 = h0 value
            } else {
                const float4* X = (const float4*)(sbuf + (d << 11)) + half * 128;
#pragma unroll 2
                for (int i = lane; i < 64; i += 32) {
                    float4 x0 = X[2 * i], x1 = X[2 * i + 1];
                    a0 += dot8q(D0[i], x0, x1);
                    a1 += dot8q(D1[i], x0, x1);
                    a2 += dot8q(D2[i], x0, x1);
                    a3 += dot8q(D3[i], x0, x1);
                }
                a0 *= dsc0; a1 *= dsc1; a2 *= dsc2; a3 *= dsc3;
            }
            a0 = wredsum(a0); a1 = wredsum(a1); a2 = wredsum(a2); a3 = wredsum(a3);
            if (half == 1 && lane == 0) {
                spar[uL][0] = a0; spar[uL][1] = a1; spar[uL][2] = a2; spar[uL][3] = a3;
            }
        }
        __syncthreads();
        if (evalid && half == 0 && lane == 0) {
            a0 += spar[uL][0]; a1 += spar[uL][1]; a2 += spar[uL][2]; a3 += spar[uL][3];
            float ig = sigmoidf_(a0 + bs0);
            float fg = sigmoidf_(a1 + bs1);
            float gg = tanhf(a2 + bs2);
            float og = sigmoidf_(a3 + bs3);
            dcc = fg * dcc + ig * gg;
            float h2 = og * tanhf(dcc);
            float* dh = d ? g_dhr[(s + 1) & 1] : g_dhf[(s + 1) & 1];
            dh[dj] = h2;
            float* orow = (d ? out_recr : out_recf) + (size_t)(255 - s) * 1024;
            orow[dj] = h2;
        }
        bar++; gsync(bar);
    }
}

extern "C" void kernel_launch(void* const* d_in, const int* in_sizes, int n_in,
                              void* d_out, int out_size) {
    (void)in_sizes; (void)n_in; (void)out_size;
    cudaFuncSetAttribute(ae_kernel, cudaFuncAttributeMaxDynamicSharedMemorySize, DSM_BYTES);
    ae_kernel<<<NBLK, NTHR, DSM_BYTES>>>(
        (const int*)d_in[0], (const int*)d_in[1], (const int*)d_in[2],
        (const float*)d_in[3], (const float*)d_in[4], (const float*)d_in[5],
        (const float*)d_in[6], (const float*)d_in[7], (const float*)d_in[8],
        (const float*)d_in[9], (const float*)d_in[10], (const float*)d_in[11],
        (const float*)d_in[12], (const float*)d_in[13], (const float*)d_in[14],
        (const float*)d_in[15], (const float*)d_in[16], (const float*)d_in[17],
        (const float*)d_in[18], (const float*)d_in[19], (const float*)d_in[20],
        (const float*)d_in[21], (const float*)d_in[22], (const float*)d_in[23],
        (const float*)d_in[24], (const float*)d_in[25],
        (float*)d_out);
}

// round 13
// speedup vs baseline: 2.2297x; 1.1360x over previous
#include <cuda_runtime.h>

#define NBLK 148
#define NTHR 896
#define NW   (NTHR / 32)
#define TW   (NBLK * NW)
#define DBLK 74            // blocks per decoder barrier domain
#define DSM_BYTES 229376   // 16KB staging + 13 units * 16KB encoder weights

// ---------------- static device scratch (no runtime allocation) ----------------
__device__ __align__(16) short g_Whh_q[8192 * 2048];     // encoder Whh, int16 (33.5MB)
__device__ __align__(16) short g_Wsum_f_q[4096 * 1024];  // recf Wih+Whh, int16 (8.4MB)
__device__ __align__(16) short g_Wsum_r_q[4096 * 1024];  // recr Wih+Whh, int16 (8.4MB)
__device__ __align__(16) float g_enc_scale[8192];        // per-row dequant scale
__device__ __align__(16) float g_dsc_f[4096];
__device__ __align__(16) float g_dsc_r[4096];
__device__ __align__(16) float g_gatesx[256 * 8192];     // enc_Wih@x + bias, all t (8.4MB)
__device__ __align__(16) float g_bsum_f[4096];
__device__ __align__(16) float g_bsum_r[4096];
__device__ __align__(16) float g_enc_bsum[8192];
__device__ __align__(16) float g_hf[2][2048];   // encoder fwd hidden (double buffered)
__device__ __align__(16) float g_hr[2][2048];   // encoder rev hidden
__device__ __align__(16) float g_common[512];
__device__ __align__(16) float g_h0f[1024];
__device__ __align__(16) float g_h0r[1024];
__device__ __align__(16) float g_dhf[2][1024];  // decoder f hidden
__device__ __align__(16) float g_dhr[2][1024];  // decoder r hidden
__device__ unsigned g_cnt_main;
__device__ unsigned g_cnt_f;
__device__ unsigned g_cnt_r;

// ---------------- barrier: monotonic counter, release-arrive / acquire-poll ----
__device__ __forceinline__ void gsyncn(unsigned* cnt, unsigned target) {
    __syncthreads();
    if (threadIdx.x == 0) {
        asm volatile("red.release.gpu.global.add.u32 [%0], %1;"
                     :: "l"(cnt), "r"(1u) : "memory");
        unsigned v;
        do {
            asm volatile("ld.acquire.gpu.global.u32 %0, [%1];"
                         : "=r"(v) : "l"(cnt) : "memory");
        } while ((int)(v - target) < 0);
    }
    __syncthreads();
}

__device__ __forceinline__ float wredsum(float v) {
#pragma unroll
    for (int o = 16; o; o >>= 1) v += __shfl_xor_sync(0xffffffffu, v, o);
    return v;
}
__device__ __forceinline__ float wredmax(float v) {
#pragma unroll
    for (int o = 16; o; o >>= 1) v = fmaxf(v, __shfl_xor_sync(0xffffffffu, v, o));
    return v;
}
__device__ __forceinline__ float sigmoidf_(float v) { return 1.0f / (1.0f + __expf(-v)); }
__device__ __forceinline__ float dot4(float4 a, float4 b) {
    return a.x * b.x + a.y * b.y + a.z * b.z + a.w * b.w;
}
// stage a run of floats (multiple of 4) into shared, bypassing L1 (fresh data)
__device__ __forceinline__ void stage4(float* dst, const float* src, int n4) {
    float4* d4 = (float4*)dst;
    const float4* s4 = (const float4*)src;
    for (int i = threadIdx.x; i < n4; i += NTHR) d4[i] = __ldcg(s4 + i);
}
// int16x8 weights: dual-direction accumulate (raw integer-valued dot; scale later)
__device__ __forceinline__ void acc8x2q(float& af, float& ar, uint4 w,
                                        float4 f0, float4 f1, float4 r0, float4 r1) {
    float c0 = (float)(short)(w.x);
    float c1 = (float)((short)(w.x >> 16));
    float c2 = (float)(short)(w.y);
    float c3 = (float)((short)(w.y >> 16));
    float c4 = (float)(short)(w.z);
    float c5 = (float)((short)(w.z >> 16));
    float c6 = (float)(short)(w.w);
    float c7 = (float)((short)(w.w >> 16));
    af += c0 * f0.x + c1 * f0.y + c2 * f0.z + c3 * f0.w
        + c4 * f1.x + c5 * f1.y + c6 * f1.z + c7 * f1.w;
    ar += c0 * r0.x + c1 * r0.y + c2 * r0.z + c3 * r0.w
        + c4 * r1.x + c5 * r1.y + c6 * r1.z + c7 * r1.w;
}
__device__ __forceinline__ float dot8q(uint4 w, float4 x0, float4 x1) {
    float c0 = (float)(short)(w.x);
    float c1 = (float)((short)(w.x >> 16));
    float c2 = (float)(short)(w.y);
    float c3 = (float)((short)(w.y >> 16));
    float c4 = (float)(short)(w.z);
    float c5 = (float)((short)(w.z >> 16));
    float c6 = (float)(short)(w.w);
    float c7 = (float)((short)(w.w >> 16));
    return c0 * x0.x + c1 * x0.y + c2 * x0.z + c3 * x0.w
         + c4 * x1.x + c5 * x1.y + c6 * x1.z + c7 * x1.w;
}
__device__ __forceinline__ unsigned pack2q(float a, float b, float inv) {
    int q0 = __float2int_rn(a * inv);
    int q1 = __float2int_rn(b * inv);
    return (unsigned)(q0 & 0xffff) | ((unsigned)q1 << 16);
}

__global__ void ae_init_kernel() { g_cnt_main = 0; g_cnt_f = 0; g_cnt_r = 0; }

__global__ void __launch_bounds__(NTHR)
ae_kernel(const int* __restrict__ x, const int* __restrict__ Vg, const int* __restrict__ Jg,
          const float* __restrict__ emb, const float* __restrict__ emb_Vg,
          const float* __restrict__ emb_Jg,
          const float* __restrict__ enc_Wih, const float* __restrict__ enc_Whh,
          const float* __restrict__ enc_bih, const float* __restrict__ enc_bhh,
          const float* __restrict__ cls_W, const float* __restrict__ cls_b,
          const float* __restrict__ latf_W, const float* __restrict__ latf_b,
          const float* __restrict__ latr_W, const float* __restrict__ latr_b,
          const float* __restrict__ mix_W, const float* __restrict__ mix_b,
          const float* __restrict__ recf_Wih, const float* __restrict__ recf_Whh,
          const float* __restrict__ recf_bih, const float* __restrict__ recf_bhh,
          const float* __restrict__ recr_Wih, const float* __restrict__ recr_Whh,
          const float* __restrict__ recr_bih, const float* __restrict__ recr_bhh,
          float* __restrict__ out) {
    extern __shared__ __align__(16) char dsm[];
    float* sbuf = (float*)dsm;                        // [0, 16KB) staging (32KB in GEMM phase)
    short* sw16 = (short*)(dsm + 16384);              // weights region
    __shared__ __align__(16) float spar[14][8];       // split-K partials (unit-local)
    const int tid = threadIdx.x;
    const int lane = tid & 31;
    const int wlocal = tid >> 5;
    const int gw = blockIdx.x * NW + wlocal;
    const int gtid = blockIdx.x * NTHR + tid;
    const int gsz = NBLK * NTHR;

    // split-K pairing: two consecutive warps serve one unit/task
    const int uL = wlocal >> 1;                     // unit index within block (0..13)
    const int half = wlocal & 1;                    // K-half this warp covers
    const int u = blockIdx.x * 14 + uL;             // global encoder unit id

    float* out_recf = out + 1280;
    float* out_recr = out + 1280 + 262144;
    float* out_embf = out + 1280 + 2 * 262144;
    float* out_embr = out + 1280 + 3 * 262144;

    unsigned km = 0;  // main barrier index

    // ---------------- phase 0: int16 quantization + gathers + init ----------------
    // encoder Whh -> int16, per-row scale (warp per row)
    for (int r = gw; r < 8192; r += TW) {
        const float4* src = (const float4*)(enc_Whh + (size_t)r * 2048);
        float m = 0.f;
        for (int i = lane; i < 512; i += 32) {
            float4 v = __ldg(src + i);
            m = fmaxf(m, fmaxf(fmaxf(fabsf(v.x), fabsf(v.y)), fmaxf(fabsf(v.z), fabsf(v.w))));
        }
        m = wredmax(m);
        if (m == 0.f) m = 1.f;
        float inv = 32767.0f / m;
        if (lane == 0) g_enc_scale[r] = m / 32767.0f;
        uint2* dst = (uint2*)(g_Whh_q + (size_t)r * 2048);
        for (int i = lane; i < 512; i += 32) {
            float4 v = __ldg(src + i);
            uint2 o2;
            o2.x = pack2q(v.x, v.y, inv);
            o2.y = pack2q(v.z, v.w, inv);
            dst[i] = o2;
        }
    }
    // decoder Wsum = Wih + Whh -> int16, per-row scale (8192 row-tasks, d = r>>12)
    for (int r = gw; r < 8192; r += TW) {
        const int d = r >> 12, row = r & 4095;
        const float4* A = (const float4*)((d ? recr_Wih : recf_Wih) + (size_t)row * 1024);
        const float4* B = (const float4*)((d ? recr_Whh : recf_Whh) + (size_t)row * 1024);
        float m = 0.f;
        for (int i = lane; i < 256; i += 32) {
            float4 a = __ldg(A + i), b = __ldg(B + i);
            float sx = a.x + b.x, sy = a.y + b.y, sz = a.z + b.z, sw = a.w + b.w;
            m = fmaxf(m, fmaxf(fmaxf(fabsf(sx), fabsf(sy)), fmaxf(fabsf(sz), fabsf(sw))));
        }
        m = wredmax(m);
        if (m == 0.f) m = 1.f;
        float inv = 32767.0f / m;
        if (lane == 0) (d ? g_dsc_r : g_dsc_f)[row] = m / 32767.0f;
        uint2* dst = (uint2*)((d ? g_Wsum_r_q : g_Wsum_f_q) + (size_t)row * 1024);
        for (int i = lane; i < 256; i += 32) {
            float4 a = __ldg(A + i), b = __ldg(B + i);
            uint2 o2;
            o2.x = pack2q(a.x + b.x, a.y + b.y, inv);
            o2.y = pack2q(a.z + b.z, a.w + b.w, inv);
            dst[i] = o2;
        }
    }
    for (int i = gtid; i < 4096; i += gsz) {
        g_bsum_f[i] = recf_bih[i] + recf_bhh[i];
        g_bsum_r[i] = recr_bih[i] + recr_bhh[i];
    }
    for (int i = gtid; i < 8192; i += gsz) g_enc_bsum[i] = enc_bih[i] + enc_bhh[i];
    for (int i = gtid; i < 256 * 1024; i += gsz) {
        int t = i >> 10, k = i & 1023;
        float v = emb[(x[t] << 10) + k];
        out_embf[i] = v;
        out_embr[((255 - t) << 10) + k] = v;
    }
    for (int k = gtid; k < 1024; k += gsz) {
        float e0 = emb[k], e1 = emb[1024 + k];
        out_recf[k] = e1;               // rec_f row 0   = end (emb[B_IDX=1])
        out_recf[255 * 1024 + k] = e0;  // rec_f row 255 = start (emb[X_IDX=0])
        out_recr[k] = e0;               // rec_r row 0   = end (emb[0])
        out_recr[255 * 1024 + k] = e1;  // rec_r row 255 = start (emb[1])
    }
    for (int k = gtid; k < 64; k += gsz) {
        float v = emb_Vg[(Vg[0] << 6) + k];
        g_h0f[k] = v; g_h0r[k] = v; out[k] = v; out[640 + k] = v;
        float jv = emb_Jg[(Jg[0] << 6) + k];
        g_h0f[576 + k] = jv; g_h0r[576 + k] = jv;
        out[576 + k] = jv; out[640 + 576 + k] = jv;
    }
    for (int k = gtid; k < 2048; k += gsz) { g_hf[0][k] = 0.f; g_hr[0][k] = 0.f; }
    km++; gsyncn(&g_cnt_main, km * NBLK);

    // ---------------- phase 0b: gates_x GEMM  (enc_Wih @ emb_f + bsum, all 256 t) ----
    // 128 blocks: tc = t-chunk of 8 timesteps (32 chunks), rg = 2048-row group (4 groups)
    if (blockIdx.x < 128) {
        const int tc = blockIdx.x & 31;
        const int rg = blockIdx.x >> 5;
        {   // stage x[8][1024] fp32 into smem (32KB at base; overwritten later by preload)
            const float4* src = (const float4*)(out_embf + (size_t)tc * 8 * 1024);
            float4* d4 = (float4*)sbuf;
            for (int i = tid; i < 2048; i += NTHR) d4[i] = __ldcg(src + i);
        }
        __syncthreads();
        const float4* SX = (const float4*)sbuf;
        const int rend = rg * 2048 + 2048;
        for (int r = rg * 2048 + wlocal; r < rend; r += NW) {
            const float4* W = (const float4*)(enc_Wih + (size_t)r * 1024);
            float a0 = 0.f, a1 = 0.f, a2 = 0.f, a3 = 0.f;
            float a4 = 0.f, a5 = 0.f, a6 = 0.f, a7 = 0.f;
#pragma unroll 4
            for (int i = lane; i < 256; i += 32) {
                float4 w = __ldg(W + i);
                a0 += dot4(w, SX[i]);        a1 += dot4(w, SX[256 + i]);
                a2 += dot4(w, SX[512 + i]);  a3 += dot4(w, SX[768 + i]);
                a4 += dot4(w, SX[1024 + i]); a5 += dot4(w, SX[1280 + i]);
                a6 += dot4(w, SX[1536 + i]); a7 += dot4(w, SX[1792 + i]);
            }
            a0 = wredsum(a0); a1 = wredsum(a1); a2 = wredsum(a2); a3 = wredsum(a3);
            a4 = wredsum(a4); a5 = wredsum(a5); a6 = wredsum(a6); a7 = wredsum(a7);
            if (lane == 0) {
                float b = g_enc_bsum[r];
                float* gp = g_gatesx + r;
                gp[(size_t)(tc * 8 + 0) * 8192] = a0 + b;
                gp[(size_t)(tc * 8 + 1) * 8192] = a1 + b;
                gp[(size_t)(tc * 8 + 2) * 8192] = a2 + b;
                gp[(size_t)(tc * 8 + 3) * 8192] = a3 + b;
                gp[(size_t)(tc * 8 + 4) * 8192] = a4 + b;
                gp[(size_t)(tc * 8 + 5) * 8192] = a5 + b;
                gp[(size_t)(tc * 8 + 6) * 8192] = a6 + b;
                gp[(size_t)(tc * 8 + 7) * 8192] = a7 + b;
            }
        }
    }
    __syncthreads();   // GEMM smem reads done before preload overwrites the region

    // ---------------- preload encoder weights for units 0..12 into smem ----------
    // layout: row = uL*4 + gate, each row 2048 int16 (256 uint4), halves contiguous
    {
        uint4* dst = (uint4*)sw16;
        const int ubase = blockIdx.x * 14;
        for (int idx = tid; idx < 13 * 4 * 256; idx += NTHR) {
            int row = idx >> 8;          // 0..51
            int r4  = idx & 255;
            int unit = row >> 2, gate = row & 3;
            int gu = ubase + unit;
            if (gu < 2048) {
                const uint4* src = (const uint4*)(g_Whh_q + ((size_t)gu + (size_t)gate * 2048) * 2048) + r4;
                dst[row * 256 + r4] = __ldcg(src);
            }
        }
    }
    km++; gsyncn(&g_cnt_main, km * NBLK);

    // ---------------- encoder: 256 steps, Whh-only (int16), split-K 2 warps/unit ----
    const bool evalid = (u < 2048);
    float ec = 0.f;   // lane0 (half0): fwd cell; lane1 (half0): rev cell
    float esc0 = 0.f, esc1 = 0.f, esc2 = 0.f, esc3 = 0.f;
    if (evalid) {
        esc0 = __ldg(&g_enc_scale[u]);
        esc1 = __ldg(&g_enc_scale[u + 2048]);
        esc2 = __ldg(&g_enc_scale[u + 4096]);
        esc3 = __ldg(&g_enc_scale[u + 6144]);
    }
#pragma unroll 1
    for (int t = 0; t < 256; t++) {
        stage4(sbuf, g_hf[t & 1], 512);          // hf at floats [0,2048)
        stage4(sbuf + 2048, g_hr[t & 1], 512);   // hr at floats [2048,4096)
        __syncthreads();
        float af0 = 0.f, af1 = 0.f, af2 = 0.f, af3 = 0.f;
        float ar0 = 0.f, ar1 = 0.f, ar2 = 0.f, ar3 = 0.f;
        float gx0 = 0.f, gx1 = 0.f, gx2 = 0.f, gx3 = 0.f;
        if (evalid) {
            if (half == 0 && lane < 2) {  // prefetch gates_x early (off the dot chain)
                const float* gx = g_gatesx + (size_t)(lane == 0 ? t : 255 - t) * 8192 + u;
                gx0 = __ldg(gx); gx1 = __ldg(gx + 2048);
                gx2 = __ldg(gx + 4096); gx3 = __ldg(gx + 6144);
            }
            const float4* HF = (const float4*)sbuf + half * 256;
            const float4* HR = (const float4*)(sbuf + 2048) + half * 256;
            if (uL < 13) {
                // weights resident in shared memory (LDS)
                const uint4* S0 = (const uint4*)sw16 + (uL * 4) * 256 + half * 128;
                const uint4* S1 = S0 + 256;
                const uint4* S2 = S0 + 512;
                const uint4* S3 = S0 + 768;
#pragma unroll 2
                for (int i = lane; i < 128; i += 32) {
                    float4 f0 = HF[2 * i], f1 = HF[2 * i + 1];
                    float4 r0 = HR[2 * i], r1 = HR[2 * i + 1];
                    acc8x2q(af0, ar0, S0[i], f0, f1, r0, r1);
                    acc8x2q(af1, ar1, S1[i], f0, f1, r0, r1);
                    acc8x2q(af2, ar2, S2[i], f0, f1, r0, r1);
                    acc8x2q(af3, ar3, S3[i], f0, f1, r0, r1);
                }
            } else {
                // 14th unit streams from L2 (16KB/block/step — negligible traffic)
                const uint4* V0 = (const uint4*)(g_Whh_q + (size_t)u * 2048) + half * 128;
                const uint4* V1 = (const uint4*)(g_Whh_q + (size_t)(u + 2048) * 2048) + half * 128;
                const uint4* V2 = (const uint4*)(g_Whh_q + (size_t)(u + 4096) * 2048) + half * 128;
                const uint4* V3 = (const uint4*)(g_Whh_q + (size_t)(u + 6144) * 2048) + half * 128;
#pragma unroll 2
                for (int i = lane; i < 128; i += 32) {
                    float4 f0 = HF[2 * i], f1 = HF[2 * i + 1];
                    float4 r0 = HR[2 * i], r1 = HR[2 * i + 1];
                    acc8x2q(af0, ar0, __ldg(V0 + i), f0, f1, r0, r1);
                    acc8x2q(af1, ar1, __ldg(V1 + i), f0, f1, r0, r1);
                    acc8x2q(af2, ar2, __ldg(V2 + i), f0, f1, r0, r1);
                    acc8x2q(af3, ar3, __ldg(V3 + i), f0, f1, r0, r1);
                }
            }
            af0 = wredsum(af0); af1 = wredsum(af1); af2 = wredsum(af2); af3 = wredsum(af3);
            ar0 = wredsum(ar0); ar1 = wredsum(ar1); ar2 = wredsum(ar2); ar3 = wredsum(ar3);
            if (half == 1 && lane == 0) {
                spar[uL][0] = af0; spar[uL][1] = af1; spar[uL][2] = af2; spar[uL][3] = af3;
                spar[uL][4] = ar0; spar[uL][5] = ar1; spar[uL][6] = ar2; spar[uL][7] = ar3;
            }
        }
        __syncthreads();
        if (evalid && half == 0 && lane < 2) {
            // lane0: fwd direction (af*, gx@t); lane1: rev direction (ar*, gx@255-t)
            float s0 = (lane == 0 ? af0 : ar0) + spar[uL][lane * 4 + 0];
            float s1 = (lane == 0 ? af1 : ar1) + spar[uL][lane * 4 + 1];
            float s2 = (lane == 0 ? af2 : ar2) + spar[uL][lane * 4 + 2];
            float s3 = (lane == 0 ? af3 : ar3) + spar[uL][lane * 4 + 3];
            float ig = sigmoidf_(s0 * esc0 + gx0);
            float fg = sigmoidf_(s1 * esc1 + gx1);
            float gg = tanhf(s2 * esc2 + gx2);
            float og = sigmoidf_(s3 * esc3 + gx3);
            ec = fg * ec + ig * gg;
            float hn = og * tanhf(ec);
            (lane == 0 ? g_hf : g_hr)[(t + 1) & 1][u] = hn;
        }
        km++; gsyncn(&g_cnt_main, km * NBLK);
    }

    // ---------------- glue phase 1: cls + lat_f + lat_r ----------------
    stage4(sbuf, g_hf[0], 512);         // hf at [0,2048)
    stage4(sbuf + 2048, g_hr[0], 512);  // hr at [2048,4096) -> concat layout
    __syncthreads();
    if (gw < 512) {
        int row = gw;
        const float4* W = (const float4*)(cls_W + (size_t)row * 4096);
        const float4* S = (const float4*)sbuf;
        float acc = 0.f;
        for (int i = lane; i < 1024; i += 32) acc += dot4(__ldg(W + i), S[i]);
        acc = wredsum(acc);
        if (lane == 0) g_common[row] = tanhf(acc + cls_b[row]);
    } else if (gw < 1024) {
        int row = gw - 512;
        const float4* W = (const float4*)(latf_W + (size_t)row * 2048);
        const float4* S = (const float4*)sbuf;
        float acc = 0.f;
        for (int i = lane; i < 512; i += 32) acc += dot4(__ldg(W + i), S[i]);
        acc = wredsum(acc);
        if (lane == 0) { float v = acc + latf_b[row]; g_h0f[64 + row] = v; out[64 + row] = v; }
    } else if (gw < 1536) {
        int row = gw - 1024;
        const float4* W = (const float4*)(latr_W + (size_t)row * 2048);
        const float4* S = (const float4*)(sbuf + 2048);
        float acc = 0.f;
        for (int i = lane; i < 512; i += 32) acc += dot4(__ldg(W + i), S[i]);
        acc = wredsum(acc);
        if (lane == 0) { float v = acc + latr_b[row]; g_h0r[64 + row] = v; out[640 + 64 + row] = v; }
    }
    km++; gsyncn(&g_cnt_main, km * NBLK);

    // ---------------- glue phase 2: mix ----------------
    stage4(sbuf, g_common, 128);
    __syncthreads();
    if (gw < 384) {
        int row = gw;
        const float4* W = (const float4*)(mix_W + (size_t)row * 512);
        const float4* S = (const float4*)sbuf;
        float acc = 0.f;
        for (int i = lane; i < 128; i += 32) acc += dot4(__ldg(W + i), S[i]);
        acc = wredsum(acc);
        if (lane == 0) { float v = acc + mix_b[row]; g_h0f[640 + row] = v; g_h0r[640 + row] = v; }
    }
    km++; gsyncn(&g_cnt_main, km * NBLK);

    // ---------------- decoders: two independent 74-block barrier domains ----------
    // blocks [0,74): decoder f;  blocks [74,148): decoder r
    const int dom = (blockIdx.x >= DBLK) ? 1 : 0;
    const int bloc = blockIdx.x - (dom ? DBLK : 0);
    const int gu = bloc * 14 + uL;                // task id within domain (0..1035)
    const bool dvalid = (gu < 1024);
    const int dj = gu;
    unsigned* dcnt = dom ? &g_cnt_r : &g_cnt_f;

    // preload this domain's decoder weights (14 tasks) into smem
    // layout: row = uL*4 + gate, each row 1024 int16 (128 uint4)
    {
        uint4* dst = (uint4*)sw16;
        const short* Wq = dom ? g_Wsum_r_q : g_Wsum_f_q;
        const int ubase = bloc * 14;
        for (int idx = tid; idx < 14 * 4 * 128; idx += NTHR) {
            int row = idx >> 7;          // 0..55
            int r4  = idx & 127;
            int task = row >> 2, gate = row & 3;
            int g2 = ubase + task;
            if (g2 < 1024) {
                const uint4* src = (const uint4*)(Wq + ((size_t)g2 + (size_t)gate * 1024) * 1024) + r4;
                dst[row * 128 + r4] = __ldcg(src);
            }
        }
    }

    float dcc = 0.f;  // lives on half0/lane0 only
    float dsc0 = 0.f, dsc1 = 0.f, dsc2 = 0.f, dsc3 = 0.f;
    float bs0 = 0.f, bs1 = 0.f, bs2 = 0.f, bs3 = 0.f;
    if (dvalid) {
        const float* dsc = dom ? g_dsc_r : g_dsc_f;
        dsc0 = __ldg(&dsc[dj]);        dsc1 = __ldg(&dsc[dj + 1024]);
        dsc2 = __ldg(&dsc[dj + 2048]); dsc3 = __ldg(&dsc[dj + 3072]);
        const float* bs = dom ? g_bsum_r : g_bsum_f;
        bs0 = __ldg(&bs[dj]);        bs1 = __ldg(&bs[dj + 1024]);
        bs2 = __ldg(&bs[dj + 2048]); bs3 = __ldg(&bs[dj + 3072]);
    }
    const uint4* D0 = (const uint4*)sw16 + (uL * 4) * 128 + half * 64;
    const uint4* D1 = D0 + 128;
    const uint4* D2 = D0 + 256;
    const uint4* D3 = D0 + 384;
    float* const dh_arr0 = dom ? g_dhr[0] : g_dhf[0];
    float* const dh_arr1 = dom ? g_dhr[1] : g_dhf[1];
    float* const out_rec = dom ? out_recr : out_recf;
#pragma unroll 1
    for (int s = 1; s <= 254; s++) {
        if (s == 1) {
            stage4(sbuf, dom ? emb + 1024 : emb, 256);       // start vec
            stage4(sbuf + 1024, dom ? g_h0r : g_h0f, 256);   // h0 (=c0)
        } else {
            stage4(sbuf, (s & 1) ? dh_arr1 : dh_arr0, 256);
        }
        __syncthreads();
        float a0 = 0.f, a1 = 0.f, a2 = 0.f, a3 = 0.f;
        if (dvalid) {
            if (s == 1) {
                // first step: prev != h, use original fp32 weights (one-time cost)
                const float4* X = (const float4*)sbuf + half * 128;
                const float* Wih = dom ? recr_Wih : recf_Wih;
                const float* Whh = dom ? recr_Whh : recf_Whh;
                const float4* R0 = (const float4*)(Wih + (size_t)dj * 1024) + half * 128;
                const float4* R1 = (const float4*)(Wih + (size_t)(dj + 1024) * 1024) + half * 128;
                const float4* R2 = (const float4*)(Wih + (size_t)(dj + 2048) * 1024) + half * 128;
                const float4* R3 = (const float4*)(Wih + (size_t)(dj + 3072) * 1024) + half * 128;
#pragma unroll 2
                for (int i = lane; i < 128; i += 32) {
                    float4 xv = X[i], w;
                    w = __ldg(R0 + i); a0 += dot4(w, xv);
                    w = __ldg(R1 + i); a1 += dot4(w, xv);
                    w = __ldg(R2 + i); a2 += dot4(w, xv);
                    w = __ldg(R3 + i); a3 += dot4(w, xv);
                }
                const float4* H = (const float4*)(sbuf + 1024) + half * 128;
                const float4* Q0 = (const float4*)(Whh + (size_t)dj * 1024) + half * 128;
                const float4* Q1 = (const float4*)(Whh + (size_t)(dj + 1024) * 1024) + half * 128;
                const float4* Q2 = (const float4*)(Whh + (size_t)(dj + 2048) * 1024) + half * 128;
                const float4* Q3 = (const float4*)(Whh + (size_t)(dj + 3072) * 1024) + half * 128;
#pragma unroll 2
                for (int i = lane; i < 128; i += 32) {
                    float4 hv = H[i], w;
                    w = __ldg(Q0 + i); a0 += dot4(w, hv);
                    w = __ldg(Q1 + i); a1 += dot4(w, hv);
                    w = __ldg(Q2 + i); a2 += dot4(w, hv);
                    w = __ldg(Q3 + i); a3 += dot4(w, hv);
                }
                if (half == 0) dcc = sbuf[1024 + dj];  // c0 = h0 value
            } else {
                const float4* X = (const float4*)sbuf + half * 128;
#pragma unroll 2
                for (int i = lane; i < 64; i += 32) {
                    float4 x0 = X[2 * i], x1 = X[2 * i + 1];
                    a0 += dot8q(D0[i], x0, x1);
                    a1 += dot8q(D1[i], x0, x1);
                    a2 += dot8q(D2[i], x0, x1);
                    a3 += dot8q(D3[i], x0, x1);
                }
                a0 *= dsc0; a1 *= dsc1; a2 *= dsc2; a3 *= dsc3;
            }
            a0 = wredsum(a0); a1 = wredsum(a1); a2 = wredsum(a2); a3 = wredsum(a3);
            if (half == 1 && lane == 0) {
                spar[uL][0] = a0; spar[uL][1] = a1; spar[uL][2] = a2; spar[uL][3] = a3;
            }
        }
        __syncthreads();
        if (dvalid && half == 0 && lane == 0) {
            a0 += spar[uL][0]; a1 += spar[uL][1]; a2 += spar[uL][2]; a3 += spar[uL][3];
            float ig = sigmoidf_(a0 + bs0);
            float fg = sigmoidf_(a1 + bs1);
            float gg = tanhf(a2 + bs2);
            float og = sigmoidf_(a3 + bs3);
            dcc = fg * dcc + ig * gg;
            float h2 = og * tanhf(dcc);
            float* dh = ((s + 1) & 1) ? dh_arr1 : dh_arr0;
            dh[dj] = h2;
            out_rec[(size_t)(255 - s) * 1024 + dj] = h2;
        }
        gsyncn(dcnt, (unsigned)s * DBLK);
    }
}

extern "C" void kernel_launch(void* const* d_in, const int* in_sizes, int n_in,
                              void* d_out, int out_size) {
    (void)in_sizes; (void)n_in; (void)out_size;
    cudaFuncSetAttribute(ae_kernel, cudaFuncAttributeMaxDynamicSharedMemorySize, DSM_BYTES);
    ae_init_kernel<<<1, 1>>>();
    ae_kernel<<<NBLK, NTHR, DSM_BYTES>>>(
        (const int*)d_in[0], (const int*)d_in[1], (const int*)d_in[2],
        (const float*)d_in[3], (const float*)d_in[4], (const float*)d_in[5],
        (const float*)d_in[6], (const float*)d_in[7], (const float*)d_in[8],
        (const float*)d_in[9], (const float*)d_in[10], (const float*)d_in[11],
        (const float*)d_in[12], (const float*)d_in[13], (const float*)d_in[14],
        (const float*)d_in[15], (const float*)d_in[16], (const float*)d_in[17],
        (const float*)d_in[18], (const float*)d_in[19], (const float*)d_in[20],
        (const float*)d_in[21], (const float*)d_in[22], (const float*)d_in[23],
        (const float*)d_in[24], (const float*)d_in[25],
        (float*)d_out);
}